// round 1
// baseline (speedup 1.0000x reference)
#include <cuda_runtime.h>

#define EMBED 1024
#define DFF   4096
#define NBATCH 4
#define SEQ   2048
#define NROWS (NBATCH * SEQ)   // 8192

// ---------------- scratch (device globals: no allocations allowed) ----------
__device__ float g_Q [NROWS * EMBED];                 // 32 MB
__device__ float g_Kp[NROWS * EMBED];                 // 32 MB
__device__ float g_Vp[NROWS * EMBED];                 // 32 MB
__device__ float g_S [(size_t)NBATCH * SEQ * SEQ];    // 64 MB (scores -> attn, in place)
__device__ float g_T [NROWS * EMBED];                 // 32 MB (ao, then ff2 out)
__device__ float g_X [NROWS * EMBED];                 // 32 MB (LN1 out)
__device__ float g_F [(size_t)NROWS * DFF];           // 128 MB (ff1 out)

// ---------------- generic tiled SGEMM --------------------------------------
// C[M,N] = A[M,K] @ B  (+bias) (+relu), row-major.
// TRANSB=0: B is [K,N].  TRANSB=1: B is [N,K] (C = A @ B^T).
// blockDim 256, tile 128x128x8, 8x8 per thread.
template<int BIAS, int RELU, int TRANSB>
__global__ void __launch_bounds__(256, 2)
gemm_kernel(const float* __restrict__ A, const float* __restrict__ B,
            const float* __restrict__ bias, float* __restrict__ C,
            int M, int N, int K,
            size_t sA, size_t sB, size_t sC)
{
    A += (size_t)blockIdx.z * sA;
    B += (size_t)blockIdx.z * sB;
    C += (size_t)blockIdx.z * sC;

    __shared__ float As[8][128];
    __shared__ float Bs[8][128];

    const int tid = threadIdx.x;
    const int tx  = tid & 15;        // 0..15 -> 8 cols each
    const int ty  = tid >> 4;        // 0..15 -> 8 rows each
    const int row0 = blockIdx.y * 128;
    const int col0 = blockIdx.x * 128;

    // A tile loader: 128 rows x 8 k, one float4 per thread
    const int aRow = tid >> 1;           // 0..127
    const int aCol = (tid & 1) << 2;     // 0 or 4
    const float* Ap = A + (size_t)(row0 + aRow) * K + aCol;

    // B tile loader
    const float* Bp;
    int bR, bC;
    if (TRANSB) {                        // B[N,K]: 128 n-rows x 8 k
        bR = tid >> 1;                   // n in tile
        bC = (tid & 1) << 2;             // k in tile
        Bp = B + (size_t)(col0 + bR) * K + bC;
    } else {                             // B[K,N]: 8 k-rows x 128 n
        bR = tid >> 5;                   // k in tile
        bC = (tid & 31) << 2;            // n in tile
        Bp = B + (size_t)bR * N + col0 + bC;
    }

    float acc[8][8];
#pragma unroll
    for (int i = 0; i < 8; i++)
#pragma unroll
        for (int j = 0; j < 8; j++) acc[i][j] = 0.f;

    for (int kt = 0; kt < K; kt += 8) {
        float4 av = *(const float4*)Ap;
        float4 bv = *(const float4*)Bp;

        As[aCol + 0][aRow] = av.x;
        As[aCol + 1][aRow] = av.y;
        As[aCol + 2][aRow] = av.z;
        As[aCol + 3][aRow] = av.w;

        if (TRANSB) {
            Bs[bC + 0][bR] = bv.x;
            Bs[bC + 1][bR] = bv.y;
            Bs[bC + 2][bR] = bv.z;
            Bs[bC + 3][bR] = bv.w;
        } else {
            *(float4*)&Bs[bR][bC] = bv;
        }
        __syncthreads();

#pragma unroll
        for (int k = 0; k < 8; k++) {
            float a[8], b[8];
            *(float4*)&a[0] = *(const float4*)&As[k][ty * 8];
            *(float4*)&a[4] = *(const float4*)&As[k][ty * 8 + 4];
            *(float4*)&b[0] = *(const float4*)&Bs[k][tx * 8];
            *(float4*)&b[4] = *(const float4*)&Bs[k][tx * 8 + 4];
#pragma unroll
            for (int i = 0; i < 8; i++)
#pragma unroll
                for (int j = 0; j < 8; j++)
                    acc[i][j] += a[i] * b[j];
        }
        __syncthreads();

        Ap += 8;
        Bp += TRANSB ? 8 : (size_t)8 * N;
    }

#pragma unroll
    for (int i = 0; i < 8; i++) {
        const int m = row0 + ty * 8 + i;
#pragma unroll
        for (int j = 0; j < 8; j += 4) {
            const int n = col0 + tx * 8 + j;
            float4 v;
            v.x = acc[i][j + 0]; v.y = acc[i][j + 1];
            v.z = acc[i][j + 2]; v.w = acc[i][j + 3];
            if (BIAS) {
                const float4 bb = *(const float4*)&bias[n];
                v.x += bb.x; v.y += bb.y; v.z += bb.z; v.w += bb.w;
            }
            if (RELU) {
                v.x = fmaxf(v.x, 0.f); v.y = fmaxf(v.y, 0.f);
                v.z = fmaxf(v.z, 0.f); v.w = fmaxf(v.w, 0.f);
            }
            *(float4*)&C[(size_t)m * N + n] = v;
        }
    }
}

// ---------------- softmax over rows of [8192, 2048], in place ---------------
__global__ void softmax_kernel(float* __restrict__ S)
{
    float* p = S + (size_t)blockIdx.x * SEQ;
    const int tid  = threadIdx.x;     // 256 threads
    const int lane = tid & 31;
    const int warp = tid >> 5;

    float4 v0 = ((float4*)p)[tid];
    float4 v1 = ((float4*)p)[tid + 256];

    __shared__ float sh[8];

    float m = fmaxf(fmaxf(fmaxf(v0.x, v0.y), fmaxf(v0.z, v0.w)),
                    fmaxf(fmaxf(v1.x, v1.y), fmaxf(v1.z, v1.w)));
#pragma unroll
    for (int o = 16; o > 0; o >>= 1) m = fmaxf(m, __shfl_xor_sync(0xffffffffu, m, o));
    if (lane == 0) sh[warp] = m;
    __syncthreads();
    if (tid < 32) {
        float t = (tid < 8) ? sh[tid] : -3.402823e38f;
#pragma unroll
        for (int o = 4; o > 0; o >>= 1) t = fmaxf(t, __shfl_xor_sync(0xffffffffu, t, o));
        if (tid == 0) sh[0] = t;
    }
    __syncthreads();
    m = sh[0];
    __syncthreads();   // sh is reused below

    v0.x = __expf(v0.x - m); v0.y = __expf(v0.y - m);
    v0.z = __expf(v0.z - m); v0.w = __expf(v0.w - m);
    v1.x = __expf(v1.x - m); v1.y = __expf(v1.y - m);
    v1.z = __expf(v1.z - m); v1.w = __expf(v1.w - m);

    float s = v0.x + v0.y + v0.z + v0.w + v1.x + v1.y + v1.z + v1.w;
#pragma unroll
    for (int o = 16; o > 0; o >>= 1) s += __shfl_xor_sync(0xffffffffu, s, o);
    if (lane == 0) sh[warp] = s;
    __syncthreads();
    if (tid < 32) {
        float t = (tid < 8) ? sh[tid] : 0.f;
#pragma unroll
        for (int o = 4; o > 0; o >>= 1) t += __shfl_xor_sync(0xffffffffu, t, o);
        if (tid == 0) sh[0] = t;
    }
    __syncthreads();
    const float r = 1.f / sh[0];

    v0.x *= r; v0.y *= r; v0.z *= r; v0.w *= r;
    v1.x *= r; v1.y *= r; v1.z *= r; v1.w *= r;
    ((float4*)p)[tid]       = v0;
    ((float4*)p)[tid + 256] = v1;
}

// ---------------- residual + layernorm: O = LN(X+Y)*g + b -------------------
__global__ void add_ln_kernel(const float* __restrict__ X, const float* __restrict__ Y,
                              const float* __restrict__ g, const float* __restrict__ b,
                              float* __restrict__ O)
{
    const size_t row = blockIdx.x;
    const int tid  = threadIdx.x;   // 256 threads, 1 float4 each (1024 elems)
    const int lane = tid & 31;
    const int warp = tid >> 5;

    const float4 x = ((const float4*)(X + row * EMBED))[tid];
    const float4 y = ((const float4*)(Y + row * EMBED))[tid];
    float4 v;
    v.x = x.x + y.x; v.y = x.y + y.y; v.z = x.z + y.z; v.w = x.w + y.w;

    float s1 = v.x + v.y + v.z + v.w;
    float s2 = v.x * v.x + v.y * v.y + v.z * v.z + v.w * v.w;

    __shared__ float sh1[8], sh2[8];
#pragma unroll
    for (int o = 16; o > 0; o >>= 1) {
        s1 += __shfl_xor_sync(0xffffffffu, s1, o);
        s2 += __shfl_xor_sync(0xffffffffu, s2, o);
    }
    if (lane == 0) { sh1[warp] = s1; sh2[warp] = s2; }
    __syncthreads();
    if (tid < 32) {
        float t1 = (tid < 8) ? sh1[tid] : 0.f;
        float t2 = (tid < 8) ? sh2[tid] : 0.f;
#pragma unroll
        for (int o = 4; o > 0; o >>= 1) {
            t1 += __shfl_xor_sync(0xffffffffu, t1, o);
            t2 += __shfl_xor_sync(0xffffffffu, t2, o);
        }
        if (tid == 0) { sh1[0] = t1; sh2[0] = t2; }
    }
    __syncthreads();

    const float inv = 1.f / (float)EMBED;
    const float mu  = sh1[0] * inv;
    const float var = sh2[0] * inv - mu * mu;
    const float r   = rsqrtf(var + 1e-5f);

    const float4 gg = ((const float4*)g)[tid];
    const float4 bb = ((const float4*)b)[tid];
    float4 o;
    o.x = (v.x - mu) * r * gg.x + bb.x;
    o.y = (v.y - mu) * r * gg.y + bb.y;
    o.z = (v.z - mu) * r * gg.z + bb.z;
    o.w = (v.w - mu) * r * gg.w + bb.w;
    ((float4*)(O + row * EMBED))[tid] = o;
}

// ---------------- launch -----------------------------------------------------
extern "C" void kernel_launch(void* const* d_in, const int* in_sizes, int n_in,
                              void* d_out, int out_size)
{
    const float* src = (const float*)d_in[0];
    const float* Wq  = (const float*)d_in[1];
    const float* bq  = (const float*)d_in[2];
    const float* Wk  = (const float*)d_in[3];
    const float* bk  = (const float*)d_in[4];
    const float* Wv  = (const float*)d_in[5];
    const float* bv  = (const float*)d_in[6];
    const float* Wo  = (const float*)d_in[7];
    const float* bo  = (const float*)d_in[8];
    const float* W1  = (const float*)d_in[9];
    const float* b1  = (const float*)d_in[10];
    const float* W2  = (const float*)d_in[11];
    const float* b2  = (const float*)d_in[12];
    const float* g1  = (const float*)d_in[13];
    const float* be1 = (const float*)d_in[14];
    const float* g2  = (const float*)d_in[15];
    const float* be2 = (const float*)d_in[16];

    float *Q, *Kp, *Vp, *S, *T, *X, *F;
    cudaGetSymbolAddress((void**)&Q,  g_Q);
    cudaGetSymbolAddress((void**)&Kp, g_Kp);
    cudaGetSymbolAddress((void**)&Vp, g_Vp);
    cudaGetSymbolAddress((void**)&S,  g_S);
    cudaGetSymbolAddress((void**)&T,  g_T);
    cudaGetSymbolAddress((void**)&X,  g_X);
    cudaGetSymbolAddress((void**)&F,  g_F);

    const dim3 blk(256);
    const size_t sQE = (size_t)SEQ * EMBED;   // per-batch Q/K/V stride
    const size_t sSS = (size_t)SEQ * SEQ;     // per-batch score stride

    // Q, K, V projections: [8192,1024] @ [1024,1024] + bias
    gemm_kernel<1,0,0><<<dim3(EMBED/128, NROWS/128), blk>>>(src, Wq, bq, Q,  NROWS, EMBED, EMBED, 0, 0, 0);
    gemm_kernel<1,0,0><<<dim3(EMBED/128, NROWS/128), blk>>>(src, Wk, bk, Kp, NROWS, EMBED, EMBED, 0, 0, 0);
    gemm_kernel<1,0,0><<<dim3(EMBED/128, NROWS/128), blk>>>(src, Wv, bv, Vp, NROWS, EMBED, EMBED, 0, 0, 0);

    // scores[b] = Q[b] @ K[b]^T   : [2048,2048] per batch
    gemm_kernel<0,0,1><<<dim3(SEQ/128, SEQ/128, NBATCH), blk>>>(Q, Kp, nullptr, S, SEQ, SEQ, EMBED, sQE, sQE, sSS);

    // softmax rows (in place)
    softmax_kernel<<<NROWS, 256>>>(S);

    // ao[b] = attn[b] @ V[b]     : [2048,1024] per batch
    gemm_kernel<0,0,0><<<dim3(EMBED/128, SEQ/128, NBATCH), blk>>>(S, Vp, nullptr, T, SEQ, EMBED, SEQ, sSS, sQE, sQE);

    // out-proj: ao @ Wo + bo  (reuse Q as scratch)
    gemm_kernel<1,0,0><<<dim3(EMBED/128, NROWS/128), blk>>>(T, Wo, bo, Q, NROWS, EMBED, EMBED, 0, 0, 0);

    // x = LN(src + aoWo)
    add_ln_kernel<<<NROWS, 256>>>(src, Q, g1, be1, X);

    // ff = relu(x @ W1 + b1)
    gemm_kernel<1,1,0><<<dim3(DFF/128, NROWS/128), blk>>>(X, W1, b1, F, NROWS, DFF, EMBED, 0, 0, 0);

    // ff @ W2 + b2
    gemm_kernel<1,0,0><<<dim3(EMBED/128, NROWS/128), blk>>>(F, W2, b2, T, NROWS, EMBED, DFF, 0, 0, 0);

    // out = LN(x + ff2)
    add_ln_kernel<<<NROWS, 256>>>(X, T, g2, be2, (float*)d_out);
}

// round 4
// speedup vs baseline: 2.5691x; 2.5691x over previous
#include <cuda_runtime.h>
#include <cstdint>

#define EMBED 1024
#define DFF   4096
#define NBATCH 4
#define SEQ   2048
#define NROWS (NBATCH * SEQ)   // 8192

// ---------------- scratch (device globals: no allocations allowed) ----------
__device__ float g_Q [NROWS * EMBED];
__device__ float g_Kp[NROWS * EMBED];
__device__ float g_Vp[NROWS * EMBED];
__device__ float g_S [(size_t)NBATCH * SEQ * SEQ];
__device__ float g_T [NROWS * EMBED];
__device__ float g_X [NROWS * EMBED];
__device__ float g_F [(size_t)NROWS * DFF];

// ---------------- helpers ----------------------------------------------------
__device__ __forceinline__ uint32_t tf32_rna(float f) {
    uint32_t u; asm("cvt.rna.tf32.f32 %0, %1;" : "=r"(u) : "f"(f)); return u;
}

#define CP16(dst, src) \
    asm volatile("cp.async.cg.shared.global [%0], [%1], 16;" :: "r"(dst), "l"(src))
#define CP_COMMIT()  asm volatile("cp.async.commit_group;" ::: "memory")
#define CP_WAIT1()   asm volatile("cp.async.wait_group 1;" ::: "memory")
#define CP_WAIT0()   asm volatile("cp.async.wait_group 0;" ::: "memory")

#define MMA_TF32(d, A0, A1, A2, A3, B0, B1) \
    asm volatile("mma.sync.aligned.m16n8k8.row.col.f32.tf32.tf32.f32 " \
        "{%0,%1,%2,%3},{%4,%5,%6,%7},{%8,%9},{%0,%1,%2,%3};" \
        : "+f"((d)[0]), "+f"((d)[1]), "+f"((d)[2]), "+f"((d)[3]) \
        : "r"(A0), "r"(A1), "r"(A2), "r"(A3), "r"(B0), "r"(B1))

// ---------------- tensor-core GEMM ------------------------------------------
// C[M,N] = A[M,K] @ B (+bias) (+relu), row-major.
// TRANSB=0: B is [K,N].  TRANSB=1: B is [N,K] (C = A @ B^T).
// SPLIT=0: plain tf32 (4 warps, warp tile 64x64).
// SPLIT=1: split tf32 hi/lo, 3 MMAs -> ~fp32 accuracy (8 warps, warp tile 64x32).
// Block tile 128x128x32, cp.async double buffer.
//
// SMEM layouts (floats), XOR-swizzled for conflict-free fragment LDS:
//   As[m][k]       at m*32  + (k ^ ((m&7)*4))      (also B when TRANSB)
//   Bs[k][n]       at k*128 + (n ^ ((k&3)*8))      (B when !TRANSB)
template<int BIAS, int RELU, int TRANSB, int SPLIT>
__global__ void __launch_bounds__(SPLIT ? 256 : 128, SPLIT ? 1 : 2)
gemm_tc(const float* __restrict__ A, const float* __restrict__ B,
        const float* __restrict__ bias, float* __restrict__ C,
        int M, int N, int K,
        size_t sA, size_t sB, size_t sC)
{
    constexpr int THREADS = SPLIT ? 256 : 128;
    constexpr int NI      = SPLIT ? 4 : 8;      // n8 tiles per warp
    constexpr int NLD     = 1024 / THREADS;     // float4 loads per tile per thread

    A += (size_t)blockIdx.z * sA;
    B += (size_t)blockIdx.z * sB;
    C += (size_t)blockIdx.z * sC;

    extern __shared__ float sm[];               // [A0|B0|A1|B1], 4096 floats each
    const uint32_t smbase = (uint32_t)__cvta_generic_to_shared(sm);

    const int tid  = threadIdx.x;
    const int lane = tid & 31;
    const int wid  = tid >> 5;
    const int g    = lane >> 2;     // group id 0..7
    const int tig  = lane & 3;      // thread in group
    const int wm   = wid & 1;       // warp m position (x64)
    const int wn   = wid >> 1;      // warp n position (x NI*8)
    const int swz  = g * 4;         // read swizzle for [r][32] layouts

    const int row0 = blockIdx.y * 128;
    const int col0 = blockIdx.x * 128;

    float acc[4][NI][4];
#pragma unroll
    for (int mi = 0; mi < 4; mi++)
#pragma unroll
        for (int ni = 0; ni < NI; ni++)
#pragma unroll
            for (int j = 0; j < 4; j++) acc[mi][ni][j] = 0.f;

    // ---- async tile loader ----
    auto issue = [&](int kt, int s) {
        const uint32_t sa = smbase + s * (8192 * 4);
        const uint32_t sb = sa + 4096 * 4;
#pragma unroll
        for (int i = 0; i < NLD; i++) {              // A: 128 rows x 32 k
            int flat = i * THREADS + tid;
            int r  = flat >> 3;
            int k0 = (flat & 7) * 4;
            const float* src = A + (size_t)(row0 + r) * K + kt + k0;
            uint32_t dst = sa + (r * 32 + (k0 ^ ((r & 7) * 4))) * 4;
            CP16(dst, src);
        }
#pragma unroll
        for (int i = 0; i < NLD; i++) {
            int flat = i * THREADS + tid;
            if (TRANSB) {                            // B[N,K]: 128 n x 32 k
                int n  = flat >> 3;
                int k0 = (flat & 7) * 4;
                const float* src = B + (size_t)(col0 + n) * K + kt + k0;
                uint32_t dst = sb + (n * 32 + (k0 ^ ((n & 7) * 4))) * 4;
                CP16(dst, src);
            } else {                                 // B[K,N]: 32 k x 128 n
                int k  = flat >> 5;
                int n0 = (flat & 31) * 4;
                const float* src = B + (size_t)(kt + k) * N + col0 + n0;
                uint32_t dst = sb + (k * 128 + (n0 ^ ((k & 3) * 8))) * 4;
                CP16(dst, src);
            }
        }
        CP_COMMIT();
    };

    // ---- compute one 32-k tile from buffer s ----
    auto compute = [&](int s) {
        const float* As = sm + s * 8192;
        const float* Bs = As + 4096;
#pragma unroll
        for (int ks = 0; ks < 4; ks++) {
            const int kk = ks * 8;
            uint32_t ah[4][4], al[4][4];
#pragma unroll
            for (int mi = 0; mi < 4; mi++) {
                const float* p0 = As + (wm * 64 + mi * 16 + g) * 32;
                const float* p1 = p0 + 8 * 32;
                const int i0 = (kk + tig) ^ swz;
                const int i1 = (kk + tig + 4) ^ swz;
                float v0 = p0[i0], v1 = p1[i0], v2 = p0[i1], v3 = p1[i1];
                ah[mi][0] = tf32_rna(v0); ah[mi][1] = tf32_rna(v1);
                ah[mi][2] = tf32_rna(v2); ah[mi][3] = tf32_rna(v3);
                if (SPLIT) {
                    al[mi][0] = tf32_rna(v0 - __uint_as_float(ah[mi][0]));
                    al[mi][1] = tf32_rna(v1 - __uint_as_float(ah[mi][1]));
                    al[mi][2] = tf32_rna(v2 - __uint_as_float(ah[mi][2]));
                    al[mi][3] = tf32_rna(v3 - __uint_as_float(ah[mi][3]));
                }
            }
#pragma unroll
            for (int ni = 0; ni < NI; ni++) {
                const int n = wn * (NI * 8) + ni * 8 + g;
                float w0, w1;
                if (TRANSB) {
                    const float* pn = Bs + n * 32;
                    w0 = pn[(kk + tig) ^ swz];
                    w1 = pn[(kk + tig + 4) ^ swz];
                } else {
                    const int nn = n ^ (tig * 8);
                    w0 = Bs[(kk + tig) * 128 + nn];
                    w1 = Bs[(kk + tig + 4) * 128 + nn];
                }
                const uint32_t bh0 = tf32_rna(w0), bh1 = tf32_rna(w1);
#pragma unroll
                for (int mi = 0; mi < 4; mi++)
                    MMA_TF32(acc[mi][ni], ah[mi][0], ah[mi][1], ah[mi][2], ah[mi][3], bh0, bh1);
                if (SPLIT) {
                    const uint32_t bl0 = tf32_rna(w0 - __uint_as_float(bh0));
                    const uint32_t bl1 = tf32_rna(w1 - __uint_as_float(bh1));
#pragma unroll
                    for (int mi = 0; mi < 4; mi++)
                        MMA_TF32(acc[mi][ni], al[mi][0], al[mi][1], al[mi][2], al[mi][3], bh0, bh1);
#pragma unroll
                    for (int mi = 0; mi < 4; mi++)
                        MMA_TF32(acc[mi][ni], ah[mi][0], ah[mi][1], ah[mi][2], ah[mi][3], bl0, bl1);
                }
            }
        }
    };

    const int ktiles = K / 32;
    issue(0, 0);
    for (int t = 0; t < ktiles; t++) {
        if (t + 1 < ktiles) { issue((t + 1) * 32, (t + 1) & 1); CP_WAIT1(); }
        else                { CP_WAIT0(); }
        __syncthreads();
        compute(t & 1);
        __syncthreads();
    }

    // ---- epilogue ----
#pragma unroll
    for (int mi = 0; mi < 4; mi++) {
        const int r0 = row0 + wm * 64 + mi * 16 + g;
#pragma unroll
        for (int ni = 0; ni < NI; ni++) {
            const int c = col0 + wn * (NI * 8) + ni * 8 + tig * 2;
            float2 v0 = make_float2(acc[mi][ni][0], acc[mi][ni][1]);
            float2 v1 = make_float2(acc[mi][ni][2], acc[mi][ni][3]);
            if (BIAS) {
                const float2 bb = *(const float2*)&bias[c];
                v0.x += bb.x; v0.y += bb.y;
                v1.x += bb.x; v1.y += bb.y;
            }
            if (RELU) {
                v0.x = fmaxf(v0.x, 0.f); v0.y = fmaxf(v0.y, 0.f);
                v1.x = fmaxf(v1.x, 0.f); v1.y = fmaxf(v1.y, 0.f);
            }
            *(float2*)&C[(size_t)r0 * N + c]       = v0;
            *(float2*)&C[(size_t)(r0 + 8) * N + c] = v1;
        }
    }
}

// ---------------- softmax over rows of [8192, 2048], in place ---------------
__global__ void softmax_kernel(float* __restrict__ S)
{
    float* p = S + (size_t)blockIdx.x * SEQ;
    const int tid  = threadIdx.x;     // 256 threads
    const int lane = tid & 31;
    const int warp = tid >> 5;

    float4 v0 = ((float4*)p)[tid];
    float4 v1 = ((float4*)p)[tid + 256];

    __shared__ float sh[8];

    float m = fmaxf(fmaxf(fmaxf(v0.x, v0.y), fmaxf(v0.z, v0.w)),
                    fmaxf(fmaxf(v1.x, v1.y), fmaxf(v1.z, v1.w)));
#pragma unroll
    for (int o = 16; o > 0; o >>= 1) m = fmaxf(m, __shfl_xor_sync(0xffffffffu, m, o));
    if (lane == 0) sh[warp] = m;
    __syncthreads();
    if (tid < 32) {
        float t = (tid < 8) ? sh[tid] : -3.402823e38f;
#pragma unroll
        for (int o = 4; o > 0; o >>= 1) t = fmaxf(t, __shfl_xor_sync(0xffffffffu, t, o));
        if (tid == 0) sh[0] = t;
    }
    __syncthreads();
    m = sh[0];
    __syncthreads();

    v0.x = __expf(v0.x - m); v0.y = __expf(v0.y - m);
    v0.z = __expf(v0.z - m); v0.w = __expf(v0.w - m);
    v1.x = __expf(v1.x - m); v1.y = __expf(v1.y - m);
    v1.z = __expf(v1.z - m); v1.w = __expf(v1.w - m);

    float s = v0.x + v0.y + v0.z + v0.w + v1.x + v1.y + v1.z + v1.w;
#pragma unroll
    for (int o = 16; o > 0; o >>= 1) s += __shfl_xor_sync(0xffffffffu, s, o);
    if (lane == 0) sh[warp] = s;
    __syncthreads();
    if (tid < 32) {
        float t = (tid < 8) ? sh[tid] : 0.f;
#pragma unroll
        for (int o = 4; o > 0; o >>= 1) t += __shfl_xor_sync(0xffffffffu, t, o);
        if (tid == 0) sh[0] = t;
    }
    __syncthreads();
    const float r = 1.f / sh[0];

    v0.x *= r; v0.y *= r; v0.z *= r; v0.w *= r;
    v1.x *= r; v1.y *= r; v1.z *= r; v1.w *= r;
    ((float4*)p)[tid]       = v0;
    ((float4*)p)[tid + 256] = v1;
}

// ---------------- residual + layernorm: O = LN(X+Y)*g + b -------------------
__global__ void add_ln_kernel(const float* __restrict__ X, const float* __restrict__ Y,
                              const float* __restrict__ g, const float* __restrict__ b,
                              float* __restrict__ O)
{
    const size_t row = blockIdx.x;
    const int tid  = threadIdx.x;   // 256 threads
    const int lane = tid & 31;
    const int warp = tid >> 5;

    const float4 x = ((const float4*)(X + row * EMBED))[tid];
    const float4 y = ((const float4*)(Y + row * EMBED))[tid];
    float4 v;
    v.x = x.x + y.x; v.y = x.y + y.y; v.z = x.z + y.z; v.w = x.w + y.w;

    float s1 = v.x + v.y + v.z + v.w;
    float s2 = v.x * v.x + v.y * v.y + v.z * v.z + v.w * v.w;

    __shared__ float sh1[8], sh2[8];
#pragma unroll
    for (int o = 16; o > 0; o >>= 1) {
        s1 += __shfl_xor_sync(0xffffffffu, s1, o);
        s2 += __shfl_xor_sync(0xffffffffu, s2, o);
    }
    if (lane == 0) { sh1[warp] = s1; sh2[warp] = s2; }
    __syncthreads();
    if (tid < 32) {
        float t1 = (tid < 8) ? sh1[tid] : 0.f;
        float t2 = (tid < 8) ? sh2[tid] : 0.f;
#pragma unroll
        for (int o = 4; o > 0; o >>= 1) {
            t1 += __shfl_xor_sync(0xffffffffu, t1, o);
            t2 += __shfl_xor_sync(0xffffffffu, t2, o);
        }
        if (tid == 0) { sh1[0] = t1; sh2[0] = t2; }
    }
    __syncthreads();

    const float inv = 1.f / (float)EMBED;
    const float mu  = sh1[0] * inv;
    const float var = sh2[0] * inv - mu * mu;
    const float r   = rsqrtf(var + 1e-5f);

    const float4 gg = ((const float4*)g)[tid];
    const float4 bb = ((const float4*)b)[tid];
    float4 o;
    o.x = (v.x - mu) * r * gg.x + bb.x;
    o.y = (v.y - mu) * r * gg.y + bb.y;
    o.z = (v.z - mu) * r * gg.z + bb.z;
    o.w = (v.w - mu) * r * gg.w + bb.w;
    ((float4*)(O + row * EMBED))[tid] = o;
}

// ---------------- launch -----------------------------------------------------
extern "C" void kernel_launch(void* const* d_in, const int* in_sizes, int n_in,
                              void* d_out, int out_size)
{
    const float* src = (const float*)d_in[0];
    const float* Wq  = (const float*)d_in[1];
    const float* bq  = (const float*)d_in[2];
    const float* Wk  = (const float*)d_in[3];
    const float* bk  = (const float*)d_in[4];
    const float* Wv  = (const float*)d_in[5];
    const float* bv  = (const float*)d_in[6];
    const float* Wo  = (const float*)d_in[7];
    const float* bo  = (const float*)d_in[8];
    const float* W1  = (const float*)d_in[9];
    const float* b1  = (const float*)d_in[10];
    const float* W2  = (const float*)d_in[11];
    const float* b2  = (const float*)d_in[12];
    const float* g1  = (const float*)d_in[13];
    const float* be1 = (const float*)d_in[14];
    const float* g2  = (const float*)d_in[15];
    const float* be2 = (const float*)d_in[16];

    float *Q, *Kp, *Vp, *S, *T, *X, *F;
    cudaGetSymbolAddress((void**)&Q,  g_Q);
    cudaGetSymbolAddress((void**)&Kp, g_Kp);
    cudaGetSymbolAddress((void**)&Vp, g_Vp);
    cudaGetSymbolAddress((void**)&S,  g_S);
    cudaGetSymbolAddress((void**)&T,  g_T);
    cudaGetSymbolAddress((void**)&X,  g_X);
    cudaGetSymbolAddress((void**)&F,  g_F);

    const int SMEM = 65536;
    cudaFuncSetAttribute(gemm_tc<1,0,0,1>, cudaFuncAttributeMaxDynamicSharedMemorySize, SMEM);
    cudaFuncSetAttribute(gemm_tc<0,0,1,1>, cudaFuncAttributeMaxDynamicSharedMemorySize, SMEM);
    cudaFuncSetAttribute(gemm_tc<0,0,0,0>, cudaFuncAttributeMaxDynamicSharedMemorySize, SMEM);
    cudaFuncSetAttribute(gemm_tc<1,0,0,0>, cudaFuncAttributeMaxDynamicSharedMemorySize, SMEM);
    cudaFuncSetAttribute(gemm_tc<1,1,0,0>, cudaFuncAttributeMaxDynamicSharedMemorySize, SMEM);

    const size_t sQE = (size_t)SEQ * EMBED;
    const size_t sSS = (size_t)SEQ * SEQ;

    // Q, K projections: SPLIT tf32 (feed softmax — need ~fp32 accuracy)
    gemm_tc<1,0,0,1><<<dim3(EMBED/128, NROWS/128), 256, SMEM>>>(src, Wq, bq, Q,  NROWS, EMBED, EMBED, 0, 0, 0);
    gemm_tc<1,0,0,1><<<dim3(EMBED/128, NROWS/128), 256, SMEM>>>(src, Wk, bk, Kp, NROWS, EMBED, EMBED, 0, 0, 0);
    // V projection: plain tf32
    gemm_tc<1,0,0,0><<<dim3(EMBED/128, NROWS/128), 128, SMEM>>>(src, Wv, bv, Vp, NROWS, EMBED, EMBED, 0, 0, 0);

    // scores[b] = Q[b] @ K[b]^T : SPLIT tf32
    gemm_tc<0,0,1,1><<<dim3(SEQ/128, SEQ/128, NBATCH), 256, SMEM>>>(Q, Kp, nullptr, S, SEQ, SEQ, EMBED, sQE, sQE, sSS);

    softmax_kernel<<<NROWS, 256>>>(S);

    // ao[b] = attn[b] @ V[b] : plain tf32
    gemm_tc<0,0,0,0><<<dim3(EMBED/128, SEQ/128, NBATCH), 128, SMEM>>>(S, Vp, nullptr, T, SEQ, EMBED, SEQ, sSS, sQE, sQE);

    // out-proj
    gemm_tc<1,0,0,0><<<dim3(EMBED/128, NROWS/128), 128, SMEM>>>(T, Wo, bo, Q, NROWS, EMBED, EMBED, 0, 0, 0);

    add_ln_kernel<<<NROWS, 256>>>(src, Q, g1, be1, X);

    // ff = relu(x @ W1 + b1)
    gemm_tc<1,1,0,0><<<dim3(DFF/128, NROWS/128), 128, SMEM>>>(X, W1, b1, F, NROWS, DFF, EMBED, 0, 0, 0);

    // ff @ W2 + b2
    gemm_tc<1,0,0,0><<<dim3(EMBED/128, NROWS/128), 128, SMEM>>>(F, W2, b2, T, NROWS, EMBED, DFF, 0, 0, 0);

    add_ln_kernel<<<NROWS, 256>>>(X, T, g2, be2, (float*)d_out);
}

// round 7
// speedup vs baseline: 3.0872x; 1.2017x over previous
#include <cuda_runtime.h>
#include <cstdint>

#define EMBED 1024
#define DFF   4096
#define NBATCH 4
#define SEQ   2048
#define NROWS (NBATCH * SEQ)   // 8192

// ---------------- scratch (device globals: no allocations allowed) ----------
__device__ float g_Q [NROWS * EMBED];
__device__ float g_Kp[NROWS * EMBED];
__device__ float g_Vp[NROWS * EMBED];
__device__ float g_S [(size_t)NBATCH * SEQ * SEQ];
__device__ float g_T [NROWS * EMBED];
__device__ float g_X [NROWS * EMBED];
__device__ float g_F [(size_t)NROWS * DFF];

// ---------------- helpers ----------------------------------------------------
__device__ __forceinline__ uint32_t tf32_rna(float f) {
    uint32_t u; asm("cvt.rna.tf32.f32 %0, %1;" : "=r"(u) : "f"(f)); return u;
}
// pack {low: e0, high: e1} as bf16x2 (first PTX source -> high half)
__device__ __forceinline__ uint32_t bfpack(float e0, float e1) {
    uint32_t d; asm("cvt.rn.bf16x2.f32 %0, %1, %2;" : "=r"(d) : "f"(e1), "f"(e0)); return d;
}
// residual pack: lo = x - bf16(x), given packed hi
__device__ __forceinline__ uint32_t bfres(float e0, float e1, uint32_t h) {
    float h0 = __uint_as_float(h << 16);
    float h1 = __uint_as_float(h & 0xffff0000u);
    return bfpack(e0 - h0, e1 - h1);
}

#define CP16(dst, src) \
    asm volatile("cp.async.cg.shared.global [%0], [%1], 16;" :: "r"(dst), "l"(src))
#define CP_COMMIT()  asm volatile("cp.async.commit_group;" ::: "memory")
#define CP_WAIT1()   asm volatile("cp.async.wait_group 1;" ::: "memory")
#define CP_WAIT0()   asm volatile("cp.async.wait_group 0;" ::: "memory")

#define MMA_TF32(d, A0, A1, A2, A3, B0, B1) \
    asm volatile("mma.sync.aligned.m16n8k8.row.col.f32.tf32.tf32.f32 " \
        "{%0,%1,%2,%3},{%4,%5,%6,%7},{%8,%9},{%0,%1,%2,%3};" \
        : "+f"((d)[0]), "+f"((d)[1]), "+f"((d)[2]), "+f"((d)[3]) \
        : "r"(A0), "r"(A1), "r"(A2), "r"(A3), "r"(B0), "r"(B1))

#define MMA_BF16(d, A0, A1, A2, A3, B0, B1) \
    asm volatile("mma.sync.aligned.m16n8k16.row.col.f32.bf16.bf16.f32 " \
        "{%0,%1,%2,%3},{%4,%5,%6,%7},{%8,%9},{%0,%1,%2,%3};" \
        : "+f"((d)[0]), "+f"((d)[1]), "+f"((d)[2]), "+f"((d)[3]) \
        : "r"(A0), "r"(A1), "r"(A2), "r"(A3), "r"(B0), "r"(B1))

// ---------------- tensor-core GEMM ------------------------------------------
// C[M,N] = A[M,K] @ B (+bias) (+relu), row-major.
// TRANSB=0: B is [K,N].  TRANSB=1: B is [N,K] (C = A @ B^T).
// MODE=0: plain tf32 (m16n8k8).
// MODE=1: bf16 3-term hi/lo (m16n8k16, 3 MMAs) -> ~16-17 bit mantissa accuracy.
// 256 threads, warp grid 2(m) x 4(n), warp tile 64x32, block tile 128x128x32,
// cp.async double buffer.
//
// SMEM (floats): element [r][k] of a 128x32 tile stored at r*32 + (k ^ ((r&7)*4))
//                element [k][n] of a 32x128 tile stored at k*128 + (n ^ ((k&3)*8))
template<int BIAS, int RELU, int TRANSB, int MODE>
__global__ void __launch_bounds__(256, MODE ? 1 : 2)
gemm_tc(const float* __restrict__ A, const float* __restrict__ B,
        const float* __restrict__ bias, float* __restrict__ C,
        int M, int N, int K,
        size_t sA, size_t sB, size_t sC)
{
    A += (size_t)blockIdx.z * sA;
    B += (size_t)blockIdx.z * sB;
    C += (size_t)blockIdx.z * sC;

    extern __shared__ float sm[];               // [A0|B0|A1|B1], 4096 floats each
    const uint32_t smbase = (uint32_t)__cvta_generic_to_shared(sm);

    const int tid  = threadIdx.x;
    const int lane = tid & 31;
    const int wid  = tid >> 5;
    const int g    = lane >> 2;     // group row 0..7
    const int tig  = lane & 3;      // thread in group
    const int wm   = wid & 1;       // warp m (x64)
    const int wn   = wid >> 1;      // warp n (x32)

    // swizzle decomposition: idx(k) = k ^ swz, swz = g*4 (bits 2..4)
    const int swz = g * 4;
    const int s16 = swz & 16, s12 = swz & 12, s24 = swz & 24, s4 = swz & 4;
    // per-thread k-offsets (compile-time-foldable against unrolled kk)
    const int vaH = (2 * tig) ^ s12;   // MODE=1: element pair base (even)
    const int vaL = tig ^ s4;          // MODE=0: scalar element base

    const int row0 = blockIdx.y * 128;
    const int col0 = blockIdx.x * 128;
    const int nwB  = wn * 32;          // warp n origin

    float acc[4][4][4];
#pragma unroll
    for (int mi = 0; mi < 4; mi++)
#pragma unroll
        for (int ni = 0; ni < 4; ni++)
#pragma unroll
            for (int j = 0; j < 4; j++) acc[mi][ni][j] = 0.f;

    // ---- async tile loader (256 threads, 4 float4 each per tile) ----
    auto issue = [&](int kt, int s) {
        const uint32_t sa = smbase + s * (8192 * 4);
        const uint32_t sb = sa + 4096 * 4;
#pragma unroll
        for (int i = 0; i < 4; i++) {                // A: 128 rows x 32 k
            int flat = i * 256 + tid;
            int r  = flat >> 3;
            int k0 = (flat & 7) * 4;
            const float* src = A + (size_t)(row0 + r) * K + kt + k0;
            uint32_t dst = sa + (r * 32 + (k0 ^ ((r & 7) * 4))) * 4;
            CP16(dst, src);
        }
#pragma unroll
        for (int i = 0; i < 4; i++) {
            int flat = i * 256 + tid;
            if (TRANSB) {                            // B[N,K]: 128 n x 32 k
                int n  = flat >> 3;
                int k0 = (flat & 7) * 4;
                const float* src = B + (size_t)(col0 + n) * K + kt + k0;
                uint32_t dst = sb + (n * 32 + (k0 ^ ((n & 7) * 4))) * 4;
                CP16(dst, src);
            } else {                                 // B[K,N]: 32 k x 128 n
                int k  = flat >> 5;
                int n0 = (flat & 31) * 4;
                const float* src = B + (size_t)(kt + k) * N + col0 + n0;
                uint32_t dst = sb + (k * 128 + (n0 ^ ((k & 3) * 8))) * 4;
                CP16(dst, src);
            }
        }
        CP_COMMIT();
    };

    // ---- compute one 32-k tile from buffer s ----
    auto compute = [&](int s) {
        const float* As = sm + s * 8192;
        const float* Bs = As + 4096;

        if (MODE == 1) {
            // ---- bf16 3-term, two k16 steps ----
#pragma unroll
            for (int ks = 0; ks < 2; ks++) {
                const int kk = ks * 16;
                const int kb = kk ^ s16;       // A-side (and TRANSB B-side) index base
                uint32_t ah[4][4], al[4][4];
#pragma unroll
                for (int mi = 0; mi < 4; mi++) {
                    const float* r0 = As + (wm * 64 + mi * 16 + g) * 32;
                    const float* r1 = r0 + 256;
                    const int i0 = kb + vaH;
                    float2 x0 = *(const float2*)(r0 + i0);         // k, k+1   (row g)
                    float2 x1 = *(const float2*)(r1 + i0);         //          (row g+8)
                    float2 x2 = *(const float2*)(r0 + (i0 ^ 8));   // k+8, k+9
                    float2 x3 = *(const float2*)(r1 + (i0 ^ 8));
                    ah[mi][0] = bfpack(x0.x, x0.y); al[mi][0] = bfres(x0.x, x0.y, ah[mi][0]);
                    ah[mi][1] = bfpack(x1.x, x1.y); al[mi][1] = bfres(x1.x, x1.y, ah[mi][1]);
                    ah[mi][2] = bfpack(x2.x, x2.y); al[mi][2] = bfres(x2.x, x2.y, ah[mi][2]);
                    ah[mi][3] = bfpack(x3.x, x3.y); al[mi][3] = bfres(x3.x, x3.y, ah[mi][3]);
                }
#pragma unroll
                for (int ni = 0; ni < 4; ni++) {
                    float e0, e1, e2, e3;
                    if (TRANSB) {
                        const float* bn = Bs + (nwB + ni * 8 + g) * 32;
                        const int i0 = kb + vaH;
                        float2 u0 = *(const float2*)(bn + i0);
                        float2 u1 = *(const float2*)(bn + (i0 ^ 8));
                        e0 = u0.x; e1 = u0.y; e2 = u1.x; e3 = u1.y;
                    } else {
                        const int n   = nwB + ni * 8 + g;
                        const int nn0 = n ^ (((2 * tig) & 3) * 8);
                        const int nn1 = nn0 ^ 8;
                        const float* bk = Bs + (kk + 2 * tig) * 128;
                        e0 = bk[nn0];
                        e1 = bk[128 + nn1];
                        e2 = bk[8 * 128 + nn0];
                        e3 = bk[9 * 128 + nn1];
                    }
                    const uint32_t bh0 = bfpack(e0, e1), bh1 = bfpack(e2, e3);
                    const uint32_t bl0 = bfres(e0, e1, bh0), bl1 = bfres(e2, e3, bh1);
#pragma unroll
                    for (int mi = 0; mi < 4; mi++)
                        MMA_BF16(acc[mi][ni], ah[mi][0], ah[mi][1], ah[mi][2], ah[mi][3], bh0, bh1);
#pragma unroll
                    for (int mi = 0; mi < 4; mi++)
                        MMA_BF16(acc[mi][ni], al[mi][0], al[mi][1], al[mi][2], al[mi][3], bh0, bh1);
#pragma unroll
                    for (int mi = 0; mi < 4; mi++)
                        MMA_BF16(acc[mi][ni], ah[mi][0], ah[mi][1], ah[mi][2], ah[mi][3], bl0, bl1);
                }
            }
        } else {
            // ---- plain tf32, four k8 steps ----
#pragma unroll
            for (int ks = 0; ks < 4; ks++) {
                const int kk = ks * 8;
                const int kb = kk ^ s24;
                uint32_t ah[4][4];
#pragma unroll
                for (int mi = 0; mi < 4; mi++) {
                    const float* r0 = As + (wm * 64 + mi * 16 + g) * 32;
                    const float* r1 = r0 + 256;
                    const int i0 = kb + vaL;
                    ah[mi][0] = tf32_rna(r0[i0]);
                    ah[mi][1] = tf32_rna(r1[i0]);
                    ah[mi][2] = tf32_rna(r0[i0 ^ 4]);
                    ah[mi][3] = tf32_rna(r1[i0 ^ 4]);
                }
#pragma unroll
                for (int ni = 0; ni < 4; ni++) {
                    float w0, w1;
                    if (TRANSB) {
                        const float* bn = Bs + (nwB + ni * 8 + g) * 32;
                        const int i0 = kb + vaL;
                        w0 = bn[i0];
                        w1 = bn[i0 ^ 4];
                    } else {
                        const int nn = (nwB + ni * 8 + g) ^ (tig * 8);
                        w0 = Bs[(kk + tig) * 128 + nn];
                        w1 = Bs[(kk + tig + 4) * 128 + nn];
                    }
                    const uint32_t b0 = tf32_rna(w0), b1 = tf32_rna(w1);
#pragma unroll
                    for (int mi = 0; mi < 4; mi++)
                        MMA_TF32(acc[mi][ni], ah[mi][0], ah[mi][1], ah[mi][2], ah[mi][3], b0, b1);
                }
            }
        }
    };

    const int ktiles = K / 32;
    issue(0, 0);
    for (int t = 0; t < ktiles; t++) {
        if (t + 1 < ktiles) { issue((t + 1) * 32, (t + 1) & 1); CP_WAIT1(); }
        else                { CP_WAIT0(); }
        __syncthreads();
        compute(t & 1);
        __syncthreads();
    }

    // ---- epilogue ----
#pragma unroll
    for (int mi = 0; mi < 4; mi++) {
        const int r0 = row0 + wm * 64 + mi * 16 + g;
#pragma unroll
        for (int ni = 0; ni < 4; ni++) {
            const int c = col0 + nwB + ni * 8 + tig * 2;
            float2 v0 = make_float2(acc[mi][ni][0], acc[mi][ni][1]);
            float2 v1 = make_float2(acc[mi][ni][2], acc[mi][ni][3]);
            if (BIAS) {
                const float2 bb = *(const float2*)&bias[c];
                v0.x += bb.x; v0.y += bb.y;
                v1.x += bb.x; v1.y += bb.y;
            }
            if (RELU) {
                v0.x = fmaxf(v0.x, 0.f); v0.y = fmaxf(v0.y, 0.f);
                v1.x = fmaxf(v1.x, 0.f); v1.y = fmaxf(v1.y, 0.f);
            }
            *(float2*)&C[(size_t)r0 * N + c]       = v0;
            *(float2*)&C[(size_t)(r0 + 8) * N + c] = v1;
        }
    }
}

// ---------------- softmax over rows of [8192, 2048], in place ---------------
__global__ void softmax_kernel(float* __restrict__ S)
{
    float* p = S + (size_t)blockIdx.x * SEQ;
    const int tid  = threadIdx.x;     // 256 threads
    const int lane = tid & 31;
    const int warp = tid >> 5;

    float4 v0 = ((float4*)p)[tid];
    float4 v1 = ((float4*)p)[tid + 256];

    __shared__ float sh[8];

    float m = fmaxf(fmaxf(fmaxf(v0.x, v0.y), fmaxf(v0.z, v0.w)),
                    fmaxf(fmaxf(v1.x, v1.y), fmaxf(v1.z, v1.w)));
#pragma unroll
    for (int o = 16; o > 0; o >>= 1) m = fmaxf(m, __shfl_xor_sync(0xffffffffu, m, o));
    if (lane == 0) sh[warp] = m;
    __syncthreads();
    if (tid < 32) {
        float t = (tid < 8) ? sh[tid] : -3.402823e38f;
#pragma unroll
        for (int o = 4; o > 0; o >>= 1) t = fmaxf(t, __shfl_xor_sync(0xffffffffu, t, o));
        if (tid == 0) sh[0] = t;
    }
    __syncthreads();
    m = sh[0];
    __syncthreads();

    v0.x = __expf(v0.x - m); v0.y = __expf(v0.y - m);
    v0.z = __expf(v0.z - m); v0.w = __expf(v0.w - m);
    v1.x = __expf(v1.x - m); v1.y = __expf(v1.y - m);
    v1.z = __expf(v1.z - m); v1.w = __expf(v1.w - m);

    float s = v0.x + v0.y + v0.z + v0.w + v1.x + v1.y + v1.z + v1.w;
#pragma unroll
    for (int o = 16; o > 0; o >>= 1) s += __shfl_xor_sync(0xffffffffu, s, o);
    if (lane == 0) sh[warp] = s;
    __syncthreads();
    if (tid < 32) {
        float t = (tid < 8) ? sh[tid] : 0.f;
#pragma unroll
        for (int o = 4; o > 0; o >>= 1) t += __shfl_xor_sync(0xffffffffu, t, o);
        if (tid == 0) sh[0] = t;
    }
    __syncthreads();
    const float r = 1.f / sh[0];

    v0.x *= r; v0.y *= r; v0.z *= r; v0.w *= r;
    v1.x *= r; v1.y *= r; v1.z *= r; v1.w *= r;
    ((float4*)p)[tid]       = v0;
    ((float4*)p)[tid + 256] = v1;
}

// ---------------- residual + layernorm: O = LN(X+Y)*g + b -------------------
__global__ void add_ln_kernel(const float* __restrict__ X, const float* __restrict__ Y,
                              const float* __restrict__ g, const float* __restrict__ b,
                              float* __restrict__ O)
{
    const size_t row = blockIdx.x;
    const int tid  = threadIdx.x;   // 256 threads
    const int lane = tid & 31;
    const int warp = tid >> 5;

    const float4 x = ((const float4*)(X + row * EMBED))[tid];
    const float4 y = ((const float4*)(Y + row * EMBED))[tid];
    float4 v;
    v.x = x.x + y.x; v.y = x.y + y.y; v.z = x.z + y.z; v.w = x.w + y.w;

    float s1 = v.x + v.y + v.z + v.w;
    float s2 = v.x * v.x + v.y * v.y + v.z * v.z + v.w * v.w;

    __shared__ float sh1[8], sh2[8];
#pragma unroll
    for (int o = 16; o > 0; o >>= 1) {
        s1 += __shfl_xor_sync(0xffffffffu, s1, o);
        s2 += __shfl_xor_sync(0xffffffffu, s2, o);
    }
    if (lane == 0) { sh1[warp] = s1; sh2[warp] = s2; }
    __syncthreads();
    if (tid < 32) {
        float t1 = (tid < 8) ? sh1[tid] : 0.f;
        float t2 = (tid < 8) ? sh2[tid] : 0.f;
#pragma unroll
        for (int o = 4; o > 0; o >>= 1) {
            t1 += __shfl_xor_sync(0xffffffffu, t1, o);
            t2 += __shfl_xor_sync(0xffffffffu, t2, o);
        }
        if (tid == 0) { sh1[0] = t1; sh2[0] = t2; }
    }
    __syncthreads();

    const float inv = 1.f / (float)EMBED;
    const float mu  = sh1[0] * inv;
    const float var = sh2[0] * inv - mu * mu;
    const float r   = rsqrtf(var + 1e-5f);

    const float4 gg = ((const float4*)g)[tid];
    const float4 bb = ((const float4*)b)[tid];
    float4 o;
    o.x = (v.x - mu) * r * gg.x + bb.x;
    o.y = (v.y - mu) * r * gg.y + bb.y;
    o.z = (v.z - mu) * r * gg.z + bb.z;
    o.w = (v.w - mu) * r * gg.w + bb.w;
    ((float4*)(O + row * EMBED))[tid] = o;
}

// ---------------- launch -----------------------------------------------------
extern "C" void kernel_launch(void* const* d_in, const int* in_sizes, int n_in,
                              void* d_out, int out_size)
{
    const float* src = (const float*)d_in[0];
    const float* Wq  = (const float*)d_in[1];
    const float* bq  = (const float*)d_in[2];
    const float* Wk  = (const float*)d_in[3];
    const float* bk  = (const float*)d_in[4];
    const float* Wv  = (const float*)d_in[5];
    const float* bv  = (const float*)d_in[6];
    const float* Wo  = (const float*)d_in[7];
    const float* bo  = (const float*)d_in[8];
    const float* W1  = (const float*)d_in[9];
    const float* b1  = (const float*)d_in[10];
    const float* W2  = (const float*)d_in[11];
    const float* b2  = (const float*)d_in[12];
    const float* g1  = (const float*)d_in[13];
    const float* be1 = (const float*)d_in[14];
    const float* g2  = (const float*)d_in[15];
    const float* be2 = (const float*)d_in[16];

    float *Q, *Kp, *Vp, *S, *T, *X, *F;
    cudaGetSymbolAddress((void**)&Q,  g_Q);
    cudaGetSymbolAddress((void**)&Kp, g_Kp);
    cudaGetSymbolAddress((void**)&Vp, g_Vp);
    cudaGetSymbolAddress((void**)&S,  g_S);
    cudaGetSymbolAddress((void**)&T,  g_T);
    cudaGetSymbolAddress((void**)&X,  g_X);
    cudaGetSymbolAddress((void**)&F,  g_F);

    const int SMEM = 65536;
    cudaFuncSetAttribute(gemm_tc<1,0,0,1>, cudaFuncAttributeMaxDynamicSharedMemorySize, SMEM);
    cudaFuncSetAttribute(gemm_tc<0,0,1,1>, cudaFuncAttributeMaxDynamicSharedMemorySize, SMEM);
    cudaFuncSetAttribute(gemm_tc<1,0,0,0>, cudaFuncAttributeMaxDynamicSharedMemorySize, SMEM);
    cudaFuncSetAttribute(gemm_tc<0,0,0,0>, cudaFuncAttributeMaxDynamicSharedMemorySize, SMEM);
    cudaFuncSetAttribute(gemm_tc<1,1,0,0>, cudaFuncAttributeMaxDynamicSharedMemorySize, SMEM);

    const size_t sQE = (size_t)SEQ * EMBED;
    const size_t sSS = (size_t)SEQ * SEQ;

    // Q, K projections: bf16 3-term (feed softmax — need high accuracy)
    gemm_tc<1,0,0,1><<<dim3(EMBED/128, NROWS/128), 256, SMEM>>>(src, Wq, bq, Q,  NROWS, EMBED, EMBED, 0, 0, 0);
    gemm_tc<1,0,0,1><<<dim3(EMBED/128, NROWS/128), 256, SMEM>>>(src, Wk, bk, Kp, NROWS, EMBED, EMBED, 0, 0, 0);
    // V projection: plain tf32
    gemm_tc<1,0,0,0><<<dim3(EMBED/128, NROWS/128), 256, SMEM>>>(src, Wv, bv, Vp, NROWS, EMBED, EMBED, 0, 0, 0);

    // scores[b] = Q[b] @ K[b]^T : bf16 3-term
    gemm_tc<0,0,1,1><<<dim3(SEQ/128, SEQ/128, NBATCH), 256, SMEM>>>(Q, Kp, nullptr, S, SEQ, SEQ, EMBED, sQE, sQE, sSS);

    softmax_kernel<<<NROWS, 256>>>(S);

    // ao[b] = attn[b] @ V[b] : plain tf32
    gemm_tc<0,0,0,0><<<dim3(EMBED/128, SEQ/128, NBATCH), 256, SMEM>>>(S, Vp, nullptr, T, SEQ, EMBED, SEQ, sSS, sQE, sQE);

    // out-proj
    gemm_tc<1,0,0,0><<<dim3(EMBED/128, NROWS/128), 256, SMEM>>>(T, Wo, bo, Q, NROWS, EMBED, EMBED, 0, 0, 0);

    add_ln_kernel<<<NROWS, 256>>>(src, Q, g1, be1, X);

    // ff = relu(x @ W1 + b1)
    gemm_tc<1,1,0,0><<<dim3(DFF/128, NROWS/128), 256, SMEM>>>(X, W1, b1, F, NROWS, DFF, EMBED, 0, 0, 0);

    // ff @ W2 + b2
    gemm_tc<1,0,0,0><<<dim3(EMBED/128, NROWS/128), 256, SMEM>>>(F, W2, b2, T, NROWS, EMBED, DFF, 0, 0, 0);

    add_ln_kernel<<<NROWS, 256>>>(X, T, g2, be2, (float*)d_out);
}

// round 8
// speedup vs baseline: 3.2358x; 1.0481x over previous
#include <cuda_runtime.h>
#include <cstdint>

#define EMBED 1024
#define DFF   4096
#define NBATCH 4
#define SEQ   2048
#define NROWS (NBATCH * SEQ)   // 8192

// ---------------- scratch (device globals: no allocations allowed) ----------
__device__ float    g_S  [(size_t)NBATCH * SEQ * SEQ];  // scores/attn (tf32-rounded)
__device__ float    g_T  [NROWS * EMBED];               // ao (rounded) then ff2 out (f32)
__device__ float    g_AO [NROWS * EMBED];               // wo-gemm out (f32)
__device__ float    g_X  [NROWS * EMBED];               // LN1 out f32 (residual)
__device__ float    g_Xr [NROWS * EMBED];               // LN1 out tf32-rounded (FF1 input)
__device__ float    g_F  [(size_t)NROWS * DFF];         // ff1 out (rounded)
__device__ float    g_Vp [NROWS * EMBED];               // V (rounded)
__device__ float    g_Sr [NROWS * EMBED];               // src tf32-rounded (Vproj input)
__device__ uint32_t g_Sh [NROWS * EMBED/2], g_Sl [NROWS * EMBED/2];   // src bf16 hi/lo
__device__ uint32_t g_Qh [NROWS * EMBED/2], g_Ql [NROWS * EMBED/2];
__device__ uint32_t g_Kh [NROWS * EMBED/2], g_Kl [NROWS * EMBED/2];
__device__ uint32_t g_Wqh[EMBED * EMBED/2], g_Wql[EMBED * EMBED/2];   // transposed pack [N][K/2]
__device__ uint32_t g_Wkh[EMBED * EMBED/2], g_Wkl[EMBED * EMBED/2];
__device__ float    g_Wvr[EMBED * EMBED], g_Wor[EMBED * EMBED];       // tf32-rounded weights
__device__ float    g_W1r[EMBED * DFF],   g_W2r[DFF * EMBED];

// ---------------- helpers ----------------------------------------------------
__device__ __forceinline__ uint32_t tf32_rna(float f) {
    uint32_t u; asm("cvt.rna.tf32.f32 %0, %1;" : "=r"(u) : "f"(f)); return u;
}
__device__ __forceinline__ float tf32r(float f) { return __uint_as_float(tf32_rna(f)); }
// pack {lo half: e0, hi half: e1} as bf16x2
__device__ __forceinline__ uint32_t bfpack(float e0, float e1) {
    uint32_t d; asm("cvt.rn.bf16x2.f32 %0, %1, %2;" : "=r"(d) : "f"(e1), "f"(e0)); return d;
}
__device__ __forceinline__ uint32_t bfres(float e0, float e1, uint32_t h) {
    float h0 = __uint_as_float(h << 16);
    float h1 = __uint_as_float(h & 0xffff0000u);
    return bfpack(e0 - h0, e1 - h1);
}

#define CP16(dst, src) \
    asm volatile("cp.async.cg.shared.global [%0], [%1], 16;" :: "r"(dst), "l"(src))
#define CP8(dst, src) \
    asm volatile("cp.async.ca.shared.global [%0], [%1], 8;" :: "r"(dst), "l"(src))
#define CP_COMMIT()  asm volatile("cp.async.commit_group;" ::: "memory")
#define CP_WAIT1()   asm volatile("cp.async.wait_group 1;" ::: "memory")
#define CP_WAIT0()   asm volatile("cp.async.wait_group 0;" ::: "memory")

#define MMA_TF32(d, A0, A1, A2, A3, B0, B1) \
    asm volatile("mma.sync.aligned.m16n8k8.row.col.f32.tf32.tf32.f32 " \
        "{%0,%1,%2,%3},{%4,%5,%6,%7},{%8,%9},{%0,%1,%2,%3};" \
        : "+f"((d)[0]), "+f"((d)[1]), "+f"((d)[2]), "+f"((d)[3]) \
        : "r"(A0), "r"(A1), "r"(A2), "r"(A3), "r"(B0), "r"(B1))

#define MMA_BF16(d, A0, A1, A2, A3, B0, B1) \
    asm volatile("mma.sync.aligned.m16n8k16.row.col.f32.bf16.bf16.f32 " \
        "{%0,%1,%2,%3},{%4,%5,%6,%7},{%8,%9},{%0,%1,%2,%3};" \
        : "+f"((d)[0]), "+f"((d)[1]), "+f"((d)[2]), "+f"((d)[3]) \
        : "r"(A0), "r"(A1), "r"(A2), "r"(A3), "r"(B0), "r"(B1))

// ============================================================================
// gemm_p: high-accuracy GEMM on PRE-PACKED bf16 hi/lo operands (3-term).
// A: [M rows][Kw words] (word = bf16x2, k-pairs). B: [N rows][Kw words] (k-major
// per n-row, i.e. effectively C = A @ B^T over k). 256 thr, warps 2m x 4n,
// warp tile 64x32, block tile 128x128x(32 k = 16 words), cp.async 8B double buf.
// Pure LDS+MMA inner loop (zero cvt).
// SMEM: per array, word w of row r at r*16 + (((w>>1) ^ (r&7))<<1 | (w&1)).
// ============================================================================
template<int OUTPACK, int BIAS>
__global__ void __launch_bounds__(256, 1)
gemm_p(const uint32_t* __restrict__ Ah, const uint32_t* __restrict__ Al,
       const uint32_t* __restrict__ Bh, const uint32_t* __restrict__ Bl,
       const float* __restrict__ bias,
       float* __restrict__ C, uint32_t* __restrict__ Ch, uint32_t* __restrict__ Cl,
       int M, int N, int Kw,
       size_t sAw, size_t sBw, size_t sCe)
{
    Ah += (size_t)blockIdx.z * sAw;  Al += (size_t)blockIdx.z * sAw;
    Bh += (size_t)blockIdx.z * sBw;  Bl += (size_t)blockIdx.z * sBw;
    if (!OUTPACK) C += (size_t)blockIdx.z * sCe;

    extern __shared__ uint32_t smp[];   // 2 bufs x 4 arrays x 2048 words = 64KB
    const uint32_t smbase = (uint32_t)__cvta_generic_to_shared(smp);

    const int tid  = threadIdx.x;
    const int lane = tid & 31;
    const int wid  = tid >> 5;
    const int g    = lane >> 2;
    const int tig  = lane & 3;
    const int wm   = wid & 1;
    const int wn   = wid >> 1;
    const int row0 = blockIdx.y * 128;
    const int col0 = blockIdx.x * 128;
    const int nwB  = wn * 32;

    // fragment word offsets for the 4 k-pair positions (c = 0,2,4,6)
    const int p0 = tig >> 1, b0 = tig & 1;
    const int wA0 = ((((0) + p0) ^ g) << 1) | b0;
    const int wA1 = ((((2) + p0) ^ g) << 1) | b0;
    const int wA2 = ((((4) + p0) ^ g) << 1) | b0;
    const int wA3 = ((((6) + p0) ^ g) << 1) | b0;

    float acc[4][4][4];
#pragma unroll
    for (int mi = 0; mi < 4; mi++)
#pragma unroll
        for (int ni = 0; ni < 4; ni++)
#pragma unroll
            for (int j = 0; j < 4; j++) acc[mi][ni][j] = 0.f;

    auto issue = [&](int ktw, int s) {
        const uint32_t sb = smbase + s * (8192 * 4);
        const uint32_t* gp[4] = { Ah, Al, Bh, Bl };
#pragma unroll
        for (int a = 0; a < 4; a++) {
            const uint32_t* P = gp[a];
            const int ro = (a < 2) ? row0 : col0;
            const uint32_t db = sb + a * (2048 * 4);
#pragma unroll
            for (int i = 0; i < 4; i++) {
                int flat = i * 256 + tid;
                int r = flat >> 3, p = flat & 7;
                const uint32_t* src = P + (size_t)(ro + r) * Kw + ktw + 2 * p;
                uint32_t dst = db + (r * 16 + ((p ^ (r & 7)) << 1)) * 4;
                CP8(dst, src);
            }
        }
        CP_COMMIT();
    };

    auto compute = [&](int s) {
        const uint32_t* sAh = smp + s * 8192;
        const uint32_t* sAl = sAh + 2048;
        const uint32_t* sBh = sAh + 4096;
        const uint32_t* sBl = sAh + 6144;
#pragma unroll
        for (int ks = 0; ks < 2; ks++) {
            const int wa = ks ? wA2 : wA0;
            const int wb = ks ? wA3 : wA1;
            uint32_t ah[4][4], al[4][4];
#pragma unroll
            for (int mi = 0; mi < 4; mi++) {
                const int ra = (wm * 64 + mi * 16 + g) * 16;
                ah[mi][0] = sAh[ra + wa];       ah[mi][1] = sAh[ra + 128 + wa];
                ah[mi][2] = sAh[ra + wb];       ah[mi][3] = sAh[ra + 128 + wb];
                al[mi][0] = sAl[ra + wa];       al[mi][1] = sAl[ra + 128 + wa];
                al[mi][2] = sAl[ra + wb];       al[mi][3] = sAl[ra + 128 + wb];
            }
#pragma unroll
            for (int ni = 0; ni < 4; ni++) {
                const int rb = (nwB + ni * 8 + g) * 16;
                const uint32_t bh0 = sBh[rb + wa], bh1 = sBh[rb + wb];
                const uint32_t bl0 = sBl[rb + wa], bl1 = sBl[rb + wb];
#pragma unroll
                for (int mi = 0; mi < 4; mi++)
                    MMA_BF16(acc[mi][ni], ah[mi][0], ah[mi][1], ah[mi][2], ah[mi][3], bh0, bh1);
#pragma unroll
                for (int mi = 0; mi < 4; mi++)
                    MMA_BF16(acc[mi][ni], al[mi][0], al[mi][1], al[mi][2], al[mi][3], bh0, bh1);
#pragma unroll
                for (int mi = 0; mi < 4; mi++)
                    MMA_BF16(acc[mi][ni], ah[mi][0], ah[mi][1], ah[mi][2], ah[mi][3], bl0, bl1);
            }
        }
    };

    const int ktiles = Kw / 16;
    issue(0, 0);
    for (int t = 0; t < ktiles; t++) {
        if (t + 1 < ktiles) { issue((t + 1) * 16, (t + 1) & 1); CP_WAIT1(); }
        else                { CP_WAIT0(); }
        __syncthreads();
        compute(t & 1);
        __syncthreads();
    }

#pragma unroll
    for (int mi = 0; mi < 4; mi++) {
        const int r0 = row0 + wm * 64 + mi * 16 + g;
#pragma unroll
        for (int ni = 0; ni < 4; ni++) {
            const int c = col0 + nwB + ni * 8 + tig * 2;
            float f0 = acc[mi][ni][0], f1 = acc[mi][ni][1];
            float f2 = acc[mi][ni][2], f3 = acc[mi][ni][3];
            if (BIAS) {
                const float2 bb = *(const float2*)&bias[c];
                f0 += bb.x; f1 += bb.y; f2 += bb.x; f3 += bb.y;
            }
            if (OUTPACK) {
                const int Nw = N >> 1, wc = c >> 1;
                uint32_t h0 = bfpack(f0, f1), h1 = bfpack(f2, f3);
                Ch[(size_t)r0 * Nw + wc]       = h0;
                Cl[(size_t)r0 * Nw + wc]       = bfres(f0, f1, h0);
                Ch[(size_t)(r0 + 8) * Nw + wc] = h1;
                Cl[(size_t)(r0 + 8) * Nw + wc] = bfres(f2, f3, h1);
            } else {
                *(float2*)&C[(size_t)r0 * N + c]       = make_float2(f0, f1);
                *(float2*)&C[(size_t)(r0 + 8) * N + c] = make_float2(f2, f3);
            }
        }
    }
}

// ============================================================================
// gemm_tc: plain tf32 GEMM, inputs PRE-ROUNDED to tf32 (raw-bit consumption,
// zero cvt). C = A[M,K] @ B[K,N] (+bias)(+relu)(+tf32-round output).
// ============================================================================
template<int BIAS, int RELU, int ROUNDOUT>
__global__ void __launch_bounds__(256, 2)
gemm_tc(const float* __restrict__ A, const float* __restrict__ B,
        const float* __restrict__ bias, float* __restrict__ C,
        int M, int N, int K,
        size_t sA, size_t sB, size_t sC)
{
    A += (size_t)blockIdx.z * sA;
    B += (size_t)blockIdx.z * sB;
    C += (size_t)blockIdx.z * sC;

    extern __shared__ float sm[];               // [A0|B0|A1|B1], 4096 floats each
    const uint32_t smbase = (uint32_t)__cvta_generic_to_shared(sm);

    const int tid  = threadIdx.x;
    const int lane = tid & 31;
    const int wid  = tid >> 5;
    const int g    = lane >> 2;
    const int tig  = lane & 3;
    const int wm   = wid & 1;
    const int wn   = wid >> 1;

    const int swz = g * 4;
    const int s24 = swz & 24, s4 = swz & 4;
    const int vaL = tig ^ s4;

    const int row0 = blockIdx.y * 128;
    const int col0 = blockIdx.x * 128;
    const int nwB  = wn * 32;

    float acc[4][4][4];
#pragma unroll
    for (int mi = 0; mi < 4; mi++)
#pragma unroll
        for (int ni = 0; ni < 4; ni++)
#pragma unroll
            for (int j = 0; j < 4; j++) acc[mi][ni][j] = 0.f;

    auto issue = [&](int kt, int s) {
        const uint32_t sa = smbase + s * (8192 * 4);
        const uint32_t sb = sa + 4096 * 4;
#pragma unroll
        for (int i = 0; i < 4; i++) {                // A: 128 rows x 32 k
            int flat = i * 256 + tid;
            int r  = flat >> 3;
            int k0 = (flat & 7) * 4;
            const float* src = A + (size_t)(row0 + r) * K + kt + k0;
            uint32_t dst = sa + (r * 32 + (k0 ^ ((r & 7) * 4))) * 4;
            CP16(dst, src);
        }
#pragma unroll
        for (int i = 0; i < 4; i++) {                // B: 32 k x 128 n
            int flat = i * 256 + tid;
            int k  = flat >> 5;
            int n0 = (flat & 31) * 4;
            const float* src = B + (size_t)(kt + k) * N + col0 + n0;
            uint32_t dst = sb + (k * 128 + (n0 ^ ((k & 3) * 8))) * 4;
            CP16(dst, src);
        }
        CP_COMMIT();
    };

    auto compute = [&](int s) {
        const float* As = sm + s * 8192;
        const float* Bs = As + 4096;
#pragma unroll
        for (int ks = 0; ks < 4; ks++) {
            const int kk = ks * 8;
            const int kb = kk ^ s24;
            uint32_t ah[4][4];
#pragma unroll
            for (int mi = 0; mi < 4; mi++) {
                const float* r0 = As + (wm * 64 + mi * 16 + g) * 32;
                const float* r1 = r0 + 256;
                const int i0 = kb + vaL;
                ah[mi][0] = __float_as_uint(r0[i0]);
                ah[mi][1] = __float_as_uint(r1[i0]);
                ah[mi][2] = __float_as_uint(r0[i0 ^ 4]);
                ah[mi][3] = __float_as_uint(r1[i0 ^ 4]);
            }
#pragma unroll
            for (int ni = 0; ni < 4; ni++) {
                const int nn = (nwB + ni * 8 + g) ^ (tig * 8);
                const uint32_t b0 = __float_as_uint(Bs[(kk + tig) * 128 + nn]);
                const uint32_t b1 = __float_as_uint(Bs[(kk + tig + 4) * 128 + nn]);
#pragma unroll
                for (int mi = 0; mi < 4; mi++)
                    MMA_TF32(acc[mi][ni], ah[mi][0], ah[mi][1], ah[mi][2], ah[mi][3], b0, b1);
            }
        }
    };

    const int ktiles = K / 32;
    issue(0, 0);
    for (int t = 0; t < ktiles; t++) {
        if (t + 1 < ktiles) { issue((t + 1) * 32, (t + 1) & 1); CP_WAIT1(); }
        else                { CP_WAIT0(); }
        __syncthreads();
        compute(t & 1);
        __syncthreads();
    }

#pragma unroll
    for (int mi = 0; mi < 4; mi++) {
        const int r0 = row0 + wm * 64 + mi * 16 + g;
#pragma unroll
        for (int ni = 0; ni < 4; ni++) {
            const int c = col0 + nwB + ni * 8 + tig * 2;
            float2 v0 = make_float2(acc[mi][ni][0], acc[mi][ni][1]);
            float2 v1 = make_float2(acc[mi][ni][2], acc[mi][ni][3]);
            if (BIAS) {
                const float2 bb = *(const float2*)&bias[c];
                v0.x += bb.x; v0.y += bb.y;
                v1.x += bb.x; v1.y += bb.y;
            }
            if (RELU) {
                v0.x = fmaxf(v0.x, 0.f); v0.y = fmaxf(v0.y, 0.f);
                v1.x = fmaxf(v1.x, 0.f); v1.y = fmaxf(v1.y, 0.f);
            }
            if (ROUNDOUT) {
                v0.x = tf32r(v0.x); v0.y = tf32r(v0.y);
                v1.x = tf32r(v1.x); v1.y = tf32r(v1.y);
            }
            *(float2*)&C[(size_t)r0 * N + c]       = v0;
            *(float2*)&C[(size_t)(r0 + 8) * N + c] = v1;
        }
    }
}

// ---------------- pre-pass kernels ------------------------------------------
// src [R x 1024] f32 -> Sh/Sl (bf16x2 hi/lo, k-pairs) + Sr (tf32-rounded f32)
__global__ void pack_src_kernel(const float* __restrict__ src,
                                uint32_t* __restrict__ Sh, uint32_t* __restrict__ Sl,
                                float* __restrict__ Sr)
{
    const size_t row = blockIdx.x;
    const int t = threadIdx.x;              // 256 threads, 2 words each (512 words/row)
#pragma unroll
    for (int j = 0; j < 2; j++) {
        const int p = t + j * 256;
        const float2 v = *(const float2*)(src + row * EMBED + 2 * p);
        uint32_t h = bfpack(v.x, v.y);
        Sh[row * (EMBED/2) + p] = h;
        Sl[row * (EMBED/2) + p] = bfres(v.x, v.y, h);
        *(float2*)(Sr + row * EMBED + 2 * p) = make_float2(tf32r(v.x), tf32r(v.y));
    }
}

// W [K x N] f32 -> Wh/Wl [N][K/2] (transposed k-pair pack). K=N=1024.
__global__ void pack_wt_kernel(const float* __restrict__ W,
                               uint32_t* __restrict__ Wh, uint32_t* __restrict__ Wl)
{
    const int n = blockIdx.x;               // 1024 blocks
    const int t = threadIdx.x;              // 256 threads, 2 pairs each
#pragma unroll
    for (int j = 0; j < 2; j++) {
        const int p = t + j * 256;          // k-pair index, 512 per row
        const float e0 = W[(size_t)(2 * p)     * EMBED + n];
        const float e1 = W[(size_t)(2 * p + 1) * EMBED + n];
        uint32_t h = bfpack(e0, e1);
        Wh[(size_t)n * (EMBED/2) + p] = h;
        Wl[(size_t)n * (EMBED/2) + p] = bfres(e0, e1, h);
    }
}

// element-wise tf32 rounding copy
__global__ void round_cp_kernel(const float* __restrict__ in, float* __restrict__ out, int n4)
{
    int i = blockIdx.x * blockDim.x + threadIdx.x;
    if (i < n4) {
        float4 v = ((const float4*)in)[i];
        v.x = tf32r(v.x); v.y = tf32r(v.y); v.z = tf32r(v.z); v.w = tf32r(v.w);
        ((float4*)out)[i] = v;
    }
}

// ---------------- softmax over rows of [8192, 2048], in place, tf32-rounded --
__global__ void softmax_kernel(float* __restrict__ S)
{
    float* p = S + (size_t)blockIdx.x * SEQ;
    const int tid  = threadIdx.x;     // 256 threads
    const int lane = tid & 31;
    const int warp = tid >> 5;

    float4 v0 = ((float4*)p)[tid];
    float4 v1 = ((float4*)p)[tid + 256];

    __shared__ float sh[8];

    float m = fmaxf(fmaxf(fmaxf(v0.x, v0.y), fmaxf(v0.z, v0.w)),
                    fmaxf(fmaxf(v1.x, v1.y), fmaxf(v1.z, v1.w)));
#pragma unroll
    for (int o = 16; o > 0; o >>= 1) m = fmaxf(m, __shfl_xor_sync(0xffffffffu, m, o));
    if (lane == 0) sh[warp] = m;
    __syncthreads();
    if (tid < 32) {
        float t = (tid < 8) ? sh[tid] : -3.402823e38f;
#pragma unroll
        for (int o = 4; o > 0; o >>= 1) t = fmaxf(t, __shfl_xor_sync(0xffffffffu, t, o));
        if (tid == 0) sh[0] = t;
    }
    __syncthreads();
    m = sh[0];
    __syncthreads();

    v0.x = __expf(v0.x - m); v0.y = __expf(v0.y - m);
    v0.z = __expf(v0.z - m); v0.w = __expf(v0.w - m);
    v1.x = __expf(v1.x - m); v1.y = __expf(v1.y - m);
    v1.z = __expf(v1.z - m); v1.w = __expf(v1.w - m);

    float s = v0.x + v0.y + v0.z + v0.w + v1.x + v1.y + v1.z + v1.w;
#pragma unroll
    for (int o = 16; o > 0; o >>= 1) s += __shfl_xor_sync(0xffffffffu, s, o);
    if (lane == 0) sh[warp] = s;
    __syncthreads();
    if (tid < 32) {
        float t = (tid < 8) ? sh[tid] : 0.f;
#pragma unroll
        for (int o = 4; o > 0; o >>= 1) t += __shfl_xor_sync(0xffffffffu, t, o);
        if (tid == 0) sh[0] = t;
    }
    __syncthreads();
    const float r = 1.f / sh[0];

    v0.x = tf32r(v0.x * r); v0.y = tf32r(v0.y * r);
    v0.z = tf32r(v0.z * r); v0.w = tf32r(v0.w * r);
    v1.x = tf32r(v1.x * r); v1.y = tf32r(v1.y * r);
    v1.z = tf32r(v1.z * r); v1.w = tf32r(v1.w * r);
    ((float4*)p)[tid]       = v0;
    ((float4*)p)[tid + 256] = v1;
}

// ---------------- residual + layernorm: O = LN(X+Y)*g + b [, O2 = tf32(O)] --
template<int WR>
__global__ void add_ln_kernel(const float* __restrict__ X, const float* __restrict__ Y,
                              const float* __restrict__ g, const float* __restrict__ b,
                              float* __restrict__ O, float* __restrict__ O2)
{
    const size_t row = blockIdx.x;
    const int tid  = threadIdx.x;   // 256 threads
    const int lane = tid & 31;
    const int warp = tid >> 5;

    const float4 x = ((const float4*)(X + row * EMBED))[tid];
    const float4 y = ((const float4*)(Y + row * EMBED))[tid];
    float4 v;
    v.x = x.x + y.x; v.y = x.y + y.y; v.z = x.z + y.z; v.w = x.w + y.w;

    float s1 = v.x + v.y + v.z + v.w;
    float s2 = v.x * v.x + v.y * v.y + v.z * v.z + v.w * v.w;

    __shared__ float sh1[8], sh2[8];
#pragma unroll
    for (int o = 16; o > 0; o >>= 1) {
        s1 += __shfl_xor_sync(0xffffffffu, s1, o);
        s2 += __shfl_xor_sync(0xffffffffu, s2, o);
    }
    if (lane == 0) { sh1[warp] = s1; sh2[warp] = s2; }
    __syncthreads();
    if (tid < 32) {
        float t1 = (tid < 8) ? sh1[tid] : 0.f;
        float t2 = (tid < 8) ? sh2[tid] : 0.f;
#pragma unroll
        for (int o = 4; o > 0; o >>= 1) {
            t1 += __shfl_xor_sync(0xffffffffu, t1, o);
            t2 += __shfl_xor_sync(0xffffffffu, t2, o);
        }
        if (tid == 0) { sh1[0] = t1; sh2[0] = t2; }
    }
    __syncthreads();

    const float inv = 1.f / (float)EMBED;
    const float mu  = sh1[0] * inv;
    const float var = sh2[0] * inv - mu * mu;
    const float r   = rsqrtf(var + 1e-5f);

    const float4 gg = ((const float4*)g)[tid];
    const float4 bb = ((const float4*)b)[tid];
    float4 o;
    o.x = (v.x - mu) * r * gg.x + bb.x;
    o.y = (v.y - mu) * r * gg.y + bb.y;
    o.z = (v.z - mu) * r * gg.z + bb.z;
    o.w = (v.w - mu) * r * gg.w + bb.w;
    ((float4*)(O + row * EMBED))[tid] = o;
    if (WR) {
        float4 o2;
        o2.x = tf32r(o.x); o2.y = tf32r(o.y); o2.z = tf32r(o.z); o2.w = tf32r(o.w);
        ((float4*)(O2 + row * EMBED))[tid] = o2;
    }
}

// ---------------- launch -----------------------------------------------------
extern "C" void kernel_launch(void* const* d_in, const int* in_sizes, int n_in,
                              void* d_out, int out_size)
{
    const float* src = (const float*)d_in[0];
    const float* Wq  = (const float*)d_in[1];
    const float* bq  = (const float*)d_in[2];
    const float* Wk  = (const float*)d_in[3];
    const float* bk  = (const float*)d_in[4];
    const float* Wv  = (const float*)d_in[5];
    const float* bv  = (const float*)d_in[6];
    const float* Wo  = (const float*)d_in[7];
    const float* bo  = (const float*)d_in[8];
    const float* W1  = (const float*)d_in[9];
    const float* b1  = (const float*)d_in[10];
    const float* W2  = (const float*)d_in[11];
    const float* b2  = (const float*)d_in[12];
    const float* g1  = (const float*)d_in[13];
    const float* be1 = (const float*)d_in[14];
    const float* g2  = (const float*)d_in[15];
    const float* be2 = (const float*)d_in[16];

    float *S, *T, *AO, *X, *Xr, *F, *Vp, *Sr;
    float *Wvr, *Wor, *W1r, *W2r;
    uint32_t *Sh, *Sl, *Qh, *Ql, *Kh, *Kl, *Wqh, *Wql, *Wkh, *Wkl;
    cudaGetSymbolAddress((void**)&S,   g_S);
    cudaGetSymbolAddress((void**)&T,   g_T);
    cudaGetSymbolAddress((void**)&AO,  g_AO);
    cudaGetSymbolAddress((void**)&X,   g_X);
    cudaGetSymbolAddress((void**)&Xr,  g_Xr);
    cudaGetSymbolAddress((void**)&F,   g_F);
    cudaGetSymbolAddress((void**)&Vp,  g_Vp);
    cudaGetSymbolAddress((void**)&Sr,  g_Sr);
    cudaGetSymbolAddress((void**)&Sh,  g_Sh);
    cudaGetSymbolAddress((void**)&Sl,  g_Sl);
    cudaGetSymbolAddress((void**)&Qh,  g_Qh);
    cudaGetSymbolAddress((void**)&Ql,  g_Ql);
    cudaGetSymbolAddress((void**)&Kh,  g_Kh);
    cudaGetSymbolAddress((void**)&Kl,  g_Kl);
    cudaGetSymbolAddress((void**)&Wqh, g_Wqh);
    cudaGetSymbolAddress((void**)&Wql, g_Wql);
    cudaGetSymbolAddress((void**)&Wkh, g_Wkh);
    cudaGetSymbolAddress((void**)&Wkl, g_Wkl);
    cudaGetSymbolAddress((void**)&Wvr, g_Wvr);
    cudaGetSymbolAddress((void**)&Wor, g_Wor);
    cudaGetSymbolAddress((void**)&W1r, g_W1r);
    cudaGetSymbolAddress((void**)&W2r, g_W2r);

    const int SMEM = 65536;
    cudaFuncSetAttribute(gemm_p<1,1>, cudaFuncAttributeMaxDynamicSharedMemorySize, SMEM);
    cudaFuncSetAttribute(gemm_p<0,0>, cudaFuncAttributeMaxDynamicSharedMemorySize, SMEM);
    cudaFuncSetAttribute(gemm_tc<1,0,1>, cudaFuncAttributeMaxDynamicSharedMemorySize, SMEM);
    cudaFuncSetAttribute(gemm_tc<0,0,1>, cudaFuncAttributeMaxDynamicSharedMemorySize, SMEM);
    cudaFuncSetAttribute(gemm_tc<1,0,0>, cudaFuncAttributeMaxDynamicSharedMemorySize, SMEM);
    cudaFuncSetAttribute(gemm_tc<1,1,1>, cudaFuncAttributeMaxDynamicSharedMemorySize, SMEM);

    const int KW = EMBED / 2;                       // 512 words
    const size_t sQEw = (size_t)SEQ * KW;           // per-batch packed stride (words)
    const size_t sSS  = (size_t)SEQ * SEQ;          // per-batch score stride (elems)
    const size_t sQE  = (size_t)SEQ * EMBED;

    // ---- pre-passes ----
    pack_src_kernel<<<NROWS, 256>>>(src, Sh, Sl, Sr);
    pack_wt_kernel<<<EMBED, 256>>>(Wq, Wqh, Wql);
    pack_wt_kernel<<<EMBED, 256>>>(Wk, Wkh, Wkl);
    round_cp_kernel<<<(EMBED*EMBED/4 + 255)/256, 256>>>(Wv, Wvr, EMBED*EMBED/4);
    round_cp_kernel<<<(EMBED*EMBED/4 + 255)/256, 256>>>(Wo, Wor, EMBED*EMBED/4);
    round_cp_kernel<<<(EMBED*DFF/4 + 255)/256, 256>>>(W1, W1r, EMBED*DFF/4);
    round_cp_kernel<<<(DFF*EMBED/4 + 255)/256, 256>>>(W2, W2r, DFF*EMBED/4);

    // ---- Q, K projections (bf16 3-term, packed in, packed out) ----
    gemm_p<1,1><<<dim3(EMBED/128, NROWS/128), 256, SMEM>>>(Sh, Sl, Wqh, Wql, bq,
        nullptr, Qh, Ql, NROWS, EMBED, KW, 0, 0, 0);
    gemm_p<1,1><<<dim3(EMBED/128, NROWS/128), 256, SMEM>>>(Sh, Sl, Wkh, Wkl, bk,
        nullptr, Kh, Kl, NROWS, EMBED, KW, 0, 0, 0);

    // ---- V projection (tf32, rounded inputs, rounded output) ----
    gemm_tc<1,0,1><<<dim3(EMBED/128, NROWS/128), 256, SMEM>>>(Sr, Wvr, bv, Vp,
        NROWS, EMBED, EMBED, 0, 0, 0);

    // ---- scores = Q @ K^T (bf16 3-term, packed in, f32 out) ----
    gemm_p<0,0><<<dim3(SEQ/128, SEQ/128, NBATCH), 256, SMEM>>>(Qh, Ql, Kh, Kl, nullptr,
        S, nullptr, nullptr, SEQ, SEQ, KW, sQEw, sQEw, sSS);

    softmax_kernel<<<NROWS, 256>>>(S);

    // ---- ao = attn @ V (tf32, rounded out -> feeds Wo gemm) ----
    gemm_tc<0,0,1><<<dim3(EMBED/128, SEQ/128, NBATCH), 256, SMEM>>>(S, Vp, nullptr, T,
        SEQ, EMBED, SEQ, sSS, sQE, sQE);

    // ---- out-proj (f32 out -> residual) ----
    gemm_tc<1,0,0><<<dim3(EMBED/128, NROWS/128), 256, SMEM>>>(T, Wor, bo, AO,
        NROWS, EMBED, EMBED, 0, 0, 0);

    add_ln_kernel<1><<<NROWS, 256>>>(src, AO, g1, be1, X, Xr);

    // ---- ff1 = relu(x @ W1 + b1) (rounded out) ----
    gemm_tc<1,1,1><<<dim3(DFF/128, NROWS/128), 256, SMEM>>>(Xr, W1r, b1, F,
        NROWS, DFF, EMBED, 0, 0, 0);

    // ---- ff2 (f32 out -> residual) ----
    gemm_tc<1,0,0><<<dim3(EMBED/128, NROWS/128), 256, SMEM>>>(F, W2r, b2, T,
        NROWS, EMBED, DFF, 0, 0, 0);

    add_ln_kernel<0><<<NROWS, 256>>>(X, T, g2, be2, (float*)d_out, nullptr);
}

// round 11
// speedup vs baseline: 4.3923x; 1.3574x over previous
#include <cuda_runtime.h>
#include <cstdint>

#define EMBED 1024
#define DFF   4096
#define NBATCH 4
#define SEQ   2048
#define NROWS (NBATCH * SEQ)   // 8192

// ---------------- scratch (device globals: no allocations allowed) ----------
__device__ float    g_S   [(size_t)NBATCH * SEQ * SEQ];    // raw scores (f32)
__device__ float    g_T   [NROWS * EMBED];                 // ff2 out (f32)
__device__ float    g_AO  [NROWS * EMBED];                 // wo-gemm out (f32)
__device__ float    g_X   [NROWS * EMBED];                 // LN1 out f32 (residual)
__device__ float    g_Vp  [NROWS * EMBED];                 // V proj out (f32)
// fp16x2 packed operands (uint32 words = 2 halves, k-pairs)
__device__ __align__(16) uint32_t g_SrcH[NROWS * EMBED/2];
__device__ __align__(16) uint32_t g_XH  [NROWS * EMBED/2];
__device__ __align__(16) uint32_t g_AoH [NROWS * EMBED/2];
__device__ __align__(16) uint32_t g_FH  [(size_t)NROWS * DFF/2];
__device__ __align__(16) uint32_t g_AtH [(size_t)NBATCH * SEQ * SEQ/2];
__device__ __align__(16) uint32_t g_VtH [(size_t)NBATCH * EMBED * SEQ/2];
__device__ __align__(16) uint32_t g_WvtH[EMBED * EMBED/2];
__device__ __align__(16) uint32_t g_WotH[EMBED * EMBED/2];
__device__ __align__(16) uint32_t g_W1tH[(size_t)DFF * EMBED/2];
__device__ __align__(16) uint32_t g_W2tH[(size_t)EMBED * DFF/2];
// bf16 hi/lo packed (scores path)
__device__ __align__(16) uint32_t g_Sh [NROWS * EMBED/2], g_Sl [NROWS * EMBED/2];
__device__ __align__(16) uint32_t g_Qh [NROWS * EMBED/2], g_Ql [NROWS * EMBED/2];
__device__ __align__(16) uint32_t g_Kh [NROWS * EMBED/2], g_Kl [NROWS * EMBED/2];
__device__ __align__(16) uint32_t g_Wqh[EMBED * EMBED/2], g_Wql[EMBED * EMBED/2];
__device__ __align__(16) uint32_t g_Wkh[EMBED * EMBED/2], g_Wkl[EMBED * EMBED/2];

// ---------------- helpers ----------------------------------------------------
__device__ __forceinline__ uint32_t bfpack(float e0, float e1) {
    uint32_t d; asm("cvt.rn.bf16x2.f32 %0, %1, %2;" : "=r"(d) : "f"(e1), "f"(e0)); return d;
}
__device__ __forceinline__ uint32_t bfres(float e0, float e1, uint32_t h) {
    float h0 = __uint_as_float(h << 16);
    float h1 = __uint_as_float(h & 0xffff0000u);
    return bfpack(e0 - h0, e1 - h1);
}
__device__ __forceinline__ uint32_t hpack(float e0, float e1) {   // lo=e0, hi=e1
    uint32_t d; asm("cvt.rn.f16x2.f32 %0, %1, %2;" : "=r"(d) : "f"(e1), "f"(e0)); return d;
}

#define CP16(dst, src) \
    asm volatile("cp.async.cg.shared.global [%0], [%1], 16;" :: "r"(dst), "l"(src))
#define CP8(dst, src) \
    asm volatile("cp.async.ca.shared.global [%0], [%1], 8;" :: "r"(dst), "l"(src))
#define CP_COMMIT()  asm volatile("cp.async.commit_group;" ::: "memory")
#define CP_WAIT1()   asm volatile("cp.async.wait_group 1;" ::: "memory")
#define CP_WAIT0()   asm volatile("cp.async.wait_group 0;" ::: "memory")

#define MMA_BF16(d, A0, A1, A2, A3, B0, B1) \
    asm volatile("mma.sync.aligned.m16n8k16.row.col.f32.bf16.bf16.f32 " \
        "{%0,%1,%2,%3},{%4,%5,%6,%7},{%8,%9},{%0,%1,%2,%3};" \
        : "+f"((d)[0]), "+f"((d)[1]), "+f"((d)[2]), "+f"((d)[3]) \
        : "r"(A0), "r"(A1), "r"(A2), "r"(A3), "r"(B0), "r"(B1))

#define MMA_F16(d, A0, A1, A2, A3, B0, B1) \
    asm volatile("mma.sync.aligned.m16n8k16.row.col.f32.f16.f16.f32 " \
        "{%0,%1,%2,%3},{%4,%5,%6,%7},{%8,%9},{%0,%1,%2,%3};" \
        : "+f"((d)[0]), "+f"((d)[1]), "+f"((d)[2]), "+f"((d)[3]) \
        : "r"(A0), "r"(A1), "r"(A2), "r"(A3), "r"(B0), "r"(B1))

// ============================================================================
// gemm_p: bf16 hi/lo 3-term GEMM (scores path). Proven in R8.
// A:[M][Kw] row pack; B:[N][Kw] k-major pack (C = A·B^T over k).
// ============================================================================
template<int OUTPACK, int BIAS>
__global__ void __launch_bounds__(256, 1)
gemm_p(const uint32_t* __restrict__ Ah, const uint32_t* __restrict__ Al,
       const uint32_t* __restrict__ Bh, const uint32_t* __restrict__ Bl,
       const float* __restrict__ bias,
       float* __restrict__ C, uint32_t* __restrict__ Ch, uint32_t* __restrict__ Cl,
       int M, int N, int Kw,
       size_t sAw, size_t sBw, size_t sCe)
{
    Ah += (size_t)blockIdx.z * sAw;  Al += (size_t)blockIdx.z * sAw;
    Bh += (size_t)blockIdx.z * sBw;  Bl += (size_t)blockIdx.z * sBw;
    if (!OUTPACK) C += (size_t)blockIdx.z * sCe;

    extern __shared__ uint32_t smp[];
    const uint32_t smbase = (uint32_t)__cvta_generic_to_shared(smp);

    const int tid  = threadIdx.x;
    const int lane = tid & 31;
    const int wid  = tid >> 5;
    const int g    = lane >> 2;
    const int tig  = lane & 3;
    const int wm   = wid & 1;
    const int wn   = wid >> 1;
    const int row0 = blockIdx.y * 128;
    const int col0 = blockIdx.x * 128;
    const int nwB  = wn * 32;

    const int p0 = tig >> 1, b0 = tig & 1;
    const int wA0 = ((((0) + p0) ^ g) << 1) | b0;
    const int wA1 = ((((2) + p0) ^ g) << 1) | b0;
    const int wA2 = ((((4) + p0) ^ g) << 1) | b0;
    const int wA3 = ((((6) + p0) ^ g) << 1) | b0;

    float acc[4][4][4];
#pragma unroll
    for (int mi = 0; mi < 4; mi++)
#pragma unroll
        for (int ni = 0; ni < 4; ni++)
#pragma unroll
            for (int j = 0; j < 4; j++) acc[mi][ni][j] = 0.f;

    auto issue = [&](int ktw, int s) {
        const uint32_t sb = smbase + s * (8192 * 4);
        const uint32_t* gp[4] = { Ah, Al, Bh, Bl };
#pragma unroll
        for (int a = 0; a < 4; a++) {
            const uint32_t* P = gp[a];
            const int ro = (a < 2) ? row0 : col0;
            const uint32_t db = sb + a * (2048 * 4);
#pragma unroll
            for (int i = 0; i < 4; i++) {
                int flat = i * 256 + tid;
                int r = flat >> 3, p = flat & 7;
                const uint32_t* src = P + (size_t)(ro + r) * Kw + ktw + 2 * p;
                uint32_t dst = db + (r * 16 + ((p ^ (r & 7)) << 1)) * 4;
                CP8(dst, src);
            }
        }
        CP_COMMIT();
    };

    auto compute = [&](int s) {
        const uint32_t* sAh = smp + s * 8192;
        const uint32_t* sAl = sAh + 2048;
        const uint32_t* sBh = sAh + 4096;
        const uint32_t* sBl = sAh + 6144;
#pragma unroll
        for (int ks = 0; ks < 2; ks++) {
            const int wa = ks ? wA2 : wA0;
            const int wb = ks ? wA3 : wA1;
            uint32_t ah[4][4], al[4][4];
#pragma unroll
            for (int mi = 0; mi < 4; mi++) {
                const int ra = (wm * 64 + mi * 16 + g) * 16;
                ah[mi][0] = sAh[ra + wa];       ah[mi][1] = sAh[ra + 128 + wa];
                ah[mi][2] = sAh[ra + wb];       ah[mi][3] = sAh[ra + 128 + wb];
                al[mi][0] = sAl[ra + wa];       al[mi][1] = sAl[ra + 128 + wa];
                al[mi][2] = sAl[ra + wb];       al[mi][3] = sAl[ra + 128 + wb];
            }
#pragma unroll
            for (int ni = 0; ni < 4; ni++) {
                const int rb = (nwB + ni * 8 + g) * 16;
                const uint32_t bh0 = sBh[rb + wa], bh1 = sBh[rb + wb];
                const uint32_t bl0 = sBl[rb + wa], bl1 = sBl[rb + wb];
#pragma unroll
                for (int mi = 0; mi < 4; mi++)
                    MMA_BF16(acc[mi][ni], ah[mi][0], ah[mi][1], ah[mi][2], ah[mi][3], bh0, bh1);
#pragma unroll
                for (int mi = 0; mi < 4; mi++)
                    MMA_BF16(acc[mi][ni], al[mi][0], al[mi][1], al[mi][2], al[mi][3], bh0, bh1);
#pragma unroll
                for (int mi = 0; mi < 4; mi++)
                    MMA_BF16(acc[mi][ni], ah[mi][0], ah[mi][1], ah[mi][2], ah[mi][3], bl0, bl1);
            }
        }
    };

    const int ktiles = Kw / 16;
    issue(0, 0);
    for (int t = 0; t < ktiles; t++) {
        if (t + 1 < ktiles) { issue((t + 1) * 16, (t + 1) & 1); CP_WAIT1(); }
        else                { CP_WAIT0(); }
        __syncthreads();
        compute(t & 1);
        __syncthreads();
    }

#pragma unroll
    for (int mi = 0; mi < 4; mi++) {
        const int r0 = row0 + wm * 64 + mi * 16 + g;
#pragma unroll
        for (int ni = 0; ni < 4; ni++) {
            const int c = col0 + nwB + ni * 8 + tig * 2;
            float f0 = acc[mi][ni][0], f1 = acc[mi][ni][1];
            float f2 = acc[mi][ni][2], f3 = acc[mi][ni][3];
            if (BIAS) {
                const float2 bb = *(const float2*)&bias[c];
                f0 += bb.x; f1 += bb.y; f2 += bb.x; f3 += bb.y;
            }
            if (OUTPACK) {
                const int Nw = N >> 1, wc = c >> 1;
                uint32_t h0 = bfpack(f0, f1), h1 = bfpack(f2, f3);
                Ch[(size_t)r0 * Nw + wc]       = h0;
                Cl[(size_t)r0 * Nw + wc]       = bfres(f0, f1, h0);
                Ch[(size_t)(r0 + 8) * Nw + wc] = h1;
                Cl[(size_t)(r0 + 8) * Nw + wc] = bfres(f2, f3, h1);
            } else {
                *(float2*)&C[(size_t)r0 * N + c]       = make_float2(f0, f1);
                *(float2*)&C[(size_t)(r0 + 8) * N + c] = make_float2(f2, f3);
            }
        }
    }
}

// ============================================================================
// gemm_h: plain fp16 GEMM on pre-packed f16x2 operands.
// A:[M][Kw] row pack; B:[N][Kw] k-major pack (C = A·B^T over k).
// Block tile 128x128x(64 k = 32 words), warps 2m x 4n (64x32), cp.async 16B
// double buffer, 2 CTAs/SM. Inner loop: pure LDS + MMA.
// SMEM: word w of row r at r*32 + ((w>>2)^(r&7))*4 + (w&3).
// ============================================================================
template<int OUTPACK, int BIAS, int RELU>
__global__ void __launch_bounds__(256, 2)
gemm_h(const uint32_t* __restrict__ A, const uint32_t* __restrict__ B,
       const float* __restrict__ bias,
       float* __restrict__ C, uint32_t* __restrict__ Cp,
       int M, int N, int Kw,
       size_t sAw, size_t sBw, size_t sCo)
{
    A += (size_t)blockIdx.z * sAw;
    B += (size_t)blockIdx.z * sBw;
    if (OUTPACK) Cp += (size_t)blockIdx.z * sCo;
    else         C  += (size_t)blockIdx.z * sCo;

    extern __shared__ uint32_t smh[];   // 2 bufs x (A 4096 + B 4096) words = 64KB
    const uint32_t smbase = (uint32_t)__cvta_generic_to_shared(smh);

    const int tid  = threadIdx.x;
    const int lane = tid & 31;
    const int wid  = tid >> 5;
    const int g    = lane >> 2;
    const int tig  = lane & 3;
    const int wm   = wid & 1;
    const int wn   = wid >> 1;
    const int row0 = blockIdx.y * 128;
    const int col0 = blockIdx.x * 128;
    const int nwB  = wn * 32;

    float acc[4][4][4];
#pragma unroll
    for (int mi = 0; mi < 4; mi++)
#pragma unroll
        for (int ni = 0; ni < 4; ni++)
#pragma unroll
            for (int j = 0; j < 4; j++) acc[mi][ni][j] = 0.f;

    auto issue = [&](int ktw, int s) {
        const uint32_t sa = smbase + s * (8192 * 4);
        const uint32_t sb = sa + 4096 * 4;
#pragma unroll
        for (int i = 0; i < 4; i++) {                 // A: 128 rows x 8 chunks
            int flat = i * 256 + tid;
            int r = flat >> 3, c = flat & 7;
            const uint32_t* src = A + (size_t)(row0 + r) * Kw + ktw + c * 4;
            uint32_t dst = sa + (r * 32 + ((c ^ (r & 7)) << 2)) * 4;
            CP16(dst, src);
        }
#pragma unroll
        for (int i = 0; i < 4; i++) {                 // B: 128 rows x 8 chunks
            int flat = i * 256 + tid;
            int r = flat >> 3, c = flat & 7;
            const uint32_t* src = B + (size_t)(col0 + r) * Kw + ktw + c * 4;
            uint32_t dst = sb + (r * 32 + ((c ^ (r & 7)) << 2)) * 4;
            CP16(dst, src);
        }
        CP_COMMIT();
    };

    auto compute = [&](int s) {
        const uint32_t* sA = smh + s * 8192;
        const uint32_t* sB = sA + 4096;
#pragma unroll
        for (int ks = 0; ks < 4; ks++) {
            const int off0 = (((2 * ks)     ^ g) << 2) + tig;
            const int off1 = (((2 * ks + 1) ^ g) << 2) + tig;
            uint32_t ah[4][4];
#pragma unroll
            for (int mi = 0; mi < 4; mi++) {
                const int ra = (wm * 64 + mi * 16 + g) * 32;
                ah[mi][0] = sA[ra + off0];       ah[mi][1] = sA[ra + 256 + off0];
                ah[mi][2] = sA[ra + off1];       ah[mi][3] = sA[ra + 256 + off1];
            }
#pragma unroll
            for (int ni = 0; ni < 4; ni++) {
                const int rb = (nwB + ni * 8 + g) * 32;
                const uint32_t b0 = sB[rb + off0], b1 = sB[rb + off1];
#pragma unroll
                for (int mi = 0; mi < 4; mi++)
                    MMA_F16(acc[mi][ni], ah[mi][0], ah[mi][1], ah[mi][2], ah[mi][3], b0, b1);
            }
        }
    };

    const int ktiles = Kw / 32;
    issue(0, 0);
    for (int t = 0; t < ktiles; t++) {
        if (t + 1 < ktiles) { issue((t + 1) * 32, (t + 1) & 1); CP_WAIT1(); }
        else                { CP_WAIT0(); }
        __syncthreads();
        compute(t & 1);
        __syncthreads();
    }

#pragma unroll
    for (int mi = 0; mi < 4; mi++) {
        const int r0 = row0 + wm * 64 + mi * 16 + g;
#pragma unroll
        for (int ni = 0; ni < 4; ni++) {
            const int c = col0 + nwB + ni * 8 + tig * 2;
            float f0 = acc[mi][ni][0], f1 = acc[mi][ni][1];
            float f2 = acc[mi][ni][2], f3 = acc[mi][ni][3];
            if (BIAS) {
                const float2 bb = *(const float2*)&bias[c];
                f0 += bb.x; f1 += bb.y; f2 += bb.x; f3 += bb.y;
            }
            if (RELU) {
                f0 = fmaxf(f0, 0.f); f1 = fmaxf(f1, 0.f);
                f2 = fmaxf(f2, 0.f); f3 = fmaxf(f3, 0.f);
            }
            if (OUTPACK) {
                const int Nw = N >> 1, wc = c >> 1;
                Cp[(size_t)r0 * Nw + wc]       = hpack(f0, f1);
                Cp[(size_t)(r0 + 8) * Nw + wc] = hpack(f2, f3);
            } else {
                *(float2*)&C[(size_t)r0 * N + c]       = make_float2(f0, f1);
                *(float2*)&C[(size_t)(r0 + 8) * N + c] = make_float2(f2, f3);
            }
        }
    }
}

// ---------------- pre-pass kernels ------------------------------------------
// src rows -> bf16 hi/lo pack + fp16 pack
__global__ void pack_src2(const float* __restrict__ src,
                          uint32_t* __restrict__ Sh, uint32_t* __restrict__ Sl,
                          uint32_t* __restrict__ SrcH)
{
    const size_t row = blockIdx.x;
    const int t = threadIdx.x;
#pragma unroll
    for (int j = 0; j < 2; j++) {
        const int p = t + j * 256;
        const float2 v = *(const float2*)(src + row * EMBED + 2 * p);
        uint32_t h = bfpack(v.x, v.y);
        Sh[row * (EMBED/2) + p] = h;
        Sl[row * (EMBED/2) + p] = bfres(v.x, v.y, h);
        SrcH[row * (EMBED/2) + p] = hpack(v.x, v.y);
    }
}

// tiled transpose-pack: A[K x N] f32 (row-major) -> At[N][K/2] fp16x2
// NOTE: tile rows are 65 floats (2-way-conflict column reads); stores into the
// tile must be SCALAR (odd rows are not 16B-aligned).
__global__ void tpack_h(const float* __restrict__ A, uint32_t* __restrict__ At,
                        int K, int N, size_t sA, size_t sAt)
{
    A  += (size_t)blockIdx.z * sA;
    At += (size_t)blockIdx.z * sAt;
    __shared__ float tile[64][65];
    const int k0 = blockIdx.y * 64, n0 = blockIdx.x * 64;
    const int t = threadIdx.x;
#pragma unroll
    for (int i = 0; i < 4; i++) {
        int flat = i * 256 + t;
        int r = flat >> 4, c = (flat & 15) * 4;
        float4 v = *(const float4*)(A + (size_t)(k0 + r) * N + n0 + c);
        tile[r][c]     = v.x;
        tile[r][c + 1] = v.y;
        tile[r][c + 2] = v.z;
        tile[r][c + 3] = v.w;
    }
    __syncthreads();
#pragma unroll
    for (int i = 0; i < 8; i++) {
        int flat = i * 256 + t;
        int n = flat >> 5, w = flat & 31;
        At[(size_t)(n0 + n) * (K >> 1) + (k0 >> 1) + w] =
            hpack(tile[2 * w][n], tile[2 * w + 1][n]);
    }
}

// tiled transpose-pack: W[K x N] f32 -> Wh/Wl[N][K/2] bf16 hi/lo
__global__ void tpack_bf(const float* __restrict__ W,
                         uint32_t* __restrict__ Wh, uint32_t* __restrict__ Wl,
                         int K, int N)
{
    __shared__ float tile[64][65];
    const int k0 = blockIdx.y * 64, n0 = blockIdx.x * 64;
    const int t = threadIdx.x;
#pragma unroll
    for (int i = 0; i < 4; i++) {
        int flat = i * 256 + t;
        int r = flat >> 4, c = (flat & 15) * 4;
        float4 v = *(const float4*)(W + (size_t)(k0 + r) * N + n0 + c);
        tile[r][c]     = v.x;
        tile[r][c + 1] = v.y;
        tile[r][c + 2] = v.z;
        tile[r][c + 3] = v.w;
    }
    __syncthreads();
#pragma unroll
    for (int i = 0; i < 8; i++) {
        int flat = i * 256 + t;
        int n = flat >> 5, w = flat & 31;
        float e0 = tile[2 * w][n], e1 = tile[2 * w + 1][n];
        uint32_t h = bfpack(e0, e1);
        Wh[(size_t)(n0 + n) * (K >> 1) + (k0 >> 1) + w] = h;
        Wl[(size_t)(n0 + n) * (K >> 1) + (k0 >> 1) + w] = bfres(e0, e1, h);
    }
}

// ---------------- softmax: read raw scores, emit packed fp16 attn ------------
__global__ void softmax_kernel(const float* __restrict__ S, uint32_t* __restrict__ AtH)
{
    const float* p = S + (size_t)blockIdx.x * SEQ;
    uint32_t* q = AtH + (size_t)blockIdx.x * (SEQ/2);
    const int tid  = threadIdx.x;     // 256 threads
    const int lane = tid & 31;
    const int warp = tid >> 5;

    float4 v0 = ((const float4*)p)[tid];
    float4 v1 = ((const float4*)p)[tid + 256];

    __shared__ float sh[8];

    float m = fmaxf(fmaxf(fmaxf(v0.x, v0.y), fmaxf(v0.z, v0.w)),
                    fmaxf(fmaxf(v1.x, v1.y), fmaxf(v1.z, v1.w)));
#pragma unroll
    for (int o = 16; o > 0; o >>= 1) m = fmaxf(m, __shfl_xor_sync(0xffffffffu, m, o));
    if (lane == 0) sh[warp] = m;
    __syncthreads();
    if (tid < 32) {
        float t = (tid < 8) ? sh[tid] : -3.402823e38f;
#pragma unroll
        for (int o = 4; o > 0; o >>= 1) t = fmaxf(t, __shfl_xor_sync(0xffffffffu, t, o));
        if (tid == 0) sh[0] = t;
    }
    __syncthreads();
    m = sh[0];
    __syncthreads();

    v0.x = __expf(v0.x - m); v0.y = __expf(v0.y - m);
    v0.z = __expf(v0.z - m); v0.w = __expf(v0.w - m);
    v1.x = __expf(v1.x - m); v1.y = __expf(v1.y - m);
    v1.z = __expf(v1.z - m); v1.w = __expf(v1.w - m);

    float s = v0.x + v0.y + v0.z + v0.w + v1.x + v1.y + v1.z + v1.w;
#pragma unroll
    for (int o = 16; o > 0; o >>= 1) s += __shfl_xor_sync(0xffffffffu, s, o);
    if (lane == 0) sh[warp] = s;
    __syncthreads();
    if (tid < 32) {
        float t = (tid < 8) ? sh[tid] : 0.f;
#pragma unroll
        for (int o = 4; o > 0; o >>= 1) t += __shfl_xor_sync(0xffffffffu, t, o);
        if (tid == 0) sh[0] = t;
    }
    __syncthreads();
    const float r = 1.f / sh[0];

    q[2*tid]           = hpack(v0.x * r, v0.y * r);
    q[2*tid + 1]       = hpack(v0.z * r, v0.w * r);
    q[512 + 2*tid]     = hpack(v1.x * r, v1.y * r);
    q[512 + 2*tid + 1] = hpack(v1.z * r, v1.w * r);
}

// ---------------- residual + layernorm: O = LN(X+Y)*g + b [, OH = fp16(O)] --
template<int WR>
__global__ void add_ln_kernel(const float* __restrict__ X, const float* __restrict__ Y,
                              const float* __restrict__ g, const float* __restrict__ b,
                              float* __restrict__ O, uint32_t* __restrict__ OH)
{
    const size_t row = blockIdx.x;
    const int tid  = threadIdx.x;   // 256 threads
    const int lane = tid & 31;
    const int warp = tid >> 5;

    const float4 x = ((const float4*)(X + row * EMBED))[tid];
    const float4 y = ((const float4*)(Y + row * EMBED))[tid];
    float4 v;
    v.x = x.x + y.x; v.y = x.y + y.y; v.z = x.z + y.z; v.w = x.w + y.w;

    float s1 = v.x + v.y + v.z + v.w;
    float s2 = v.x * v.x + v.y * v.y + v.z * v.z + v.w * v.w;

    __shared__ float sh1[8], sh2[8];
#pragma unroll
    for (int o = 16; o > 0; o >>= 1) {
        s1 += __shfl_xor_sync(0xffffffffu, s1, o);
        s2 += __shfl_xor_sync(0xffffffffu, s2, o);
    }
    if (lane == 0) { sh1[warp] = s1; sh2[warp] = s2; }
    __syncthreads();
    if (tid < 32) {
        float t1 = (tid < 8) ? sh1[tid] : 0.f;
        float t2 = (tid < 8) ? sh2[tid] : 0.f;
#pragma unroll
        for (int o = 4; o > 0; o >>= 1) {
            t1 += __shfl_xor_sync(0xffffffffu, t1, o);
            t2 += __shfl_xor_sync(0xffffffffu, t2, o);
        }
        if (tid == 0) { sh1[0] = t1; sh2[0] = t2; }
    }
    __syncthreads();

    const float inv = 1.f / (float)EMBED;
    const float mu  = sh1[0] * inv;
    const float var = sh2[0] * inv - mu * mu;
    const float r   = rsqrtf(var + 1e-5f);

    const float4 gg = ((const float4*)g)[tid];
    const float4 bb = ((const float4*)b)[tid];
    float4 o;
    o.x = (v.x - mu) * r * gg.x + bb.x;
    o.y = (v.y - mu) * r * gg.y + bb.y;
    o.z = (v.z - mu) * r * gg.z + bb.z;
    o.w = (v.w - mu) * r * gg.w + bb.w;
    ((float4*)(O + row * EMBED))[tid] = o;
    if (WR) {
        OH[row * (EMBED/2) + 2*tid]     = hpack(o.x, o.y);
        OH[row * (EMBED/2) + 2*tid + 1] = hpack(o.z, o.w);
    }
}

// ---------------- launch -----------------------------------------------------
extern "C" void kernel_launch(void* const* d_in, const int* in_sizes, int n_in,
                              void* d_out, int out_size)
{
    const float* src = (const float*)d_in[0];
    const float* Wq  = (const float*)d_in[1];
    const float* bq  = (const float*)d_in[2];
    const float* Wk  = (const float*)d_in[3];
    const float* bk  = (const float*)d_in[4];
    const float* Wv  = (const float*)d_in[5];
    const float* bv  = (const float*)d_in[6];
    const float* Wo  = (const float*)d_in[7];
    const float* bo  = (const float*)d_in[8];
    const float* W1  = (const float*)d_in[9];
    const float* b1  = (const float*)d_in[10];
    const float* W2  = (const float*)d_in[11];
    const float* b2  = (const float*)d_in[12];
    const float* g1  = (const float*)d_in[13];
    const float* be1 = (const float*)d_in[14];
    const float* g2  = (const float*)d_in[15];
    const float* be2 = (const float*)d_in[16];

    float *S, *T, *AO, *X, *Vp;
    uint32_t *SrcH, *XH, *AoH, *FH, *AtH, *VtH, *WvtH, *WotH, *W1tH, *W2tH;
    uint32_t *Sh, *Sl, *Qh, *Ql, *Kh, *Kl, *Wqh, *Wql, *Wkh, *Wkl;
    cudaGetSymbolAddress((void**)&S,    g_S);
    cudaGetSymbolAddress((void**)&T,    g_T);
    cudaGetSymbolAddress((void**)&AO,   g_AO);
    cudaGetSymbolAddress((void**)&X,    g_X);
    cudaGetSymbolAddress((void**)&Vp,   g_Vp);
    cudaGetSymbolAddress((void**)&SrcH, g_SrcH);
    cudaGetSymbolAddress((void**)&XH,   g_XH);
    cudaGetSymbolAddress((void**)&AoH,  g_AoH);
    cudaGetSymbolAddress((void**)&FH,   g_FH);
    cudaGetSymbolAddress((void**)&AtH,  g_AtH);
    cudaGetSymbolAddress((void**)&VtH,  g_VtH);
    cudaGetSymbolAddress((void**)&WvtH, g_WvtH);
    cudaGetSymbolAddress((void**)&WotH, g_WotH);
    cudaGetSymbolAddress((void**)&W1tH, g_W1tH);
    cudaGetSymbolAddress((void**)&W2tH, g_W2tH);
    cudaGetSymbolAddress((void**)&Sh,   g_Sh);
    cudaGetSymbolAddress((void**)&Sl,   g_Sl);
    cudaGetSymbolAddress((void**)&Qh,   g_Qh);
    cudaGetSymbolAddress((void**)&Ql,   g_Ql);
    cudaGetSymbolAddress((void**)&Kh,   g_Kh);
    cudaGetSymbolAddress((void**)&Kl,   g_Kl);
    cudaGetSymbolAddress((void**)&Wqh,  g_Wqh);
    cudaGetSymbolAddress((void**)&Wql,  g_Wql);
    cudaGetSymbolAddress((void**)&Wkh,  g_Wkh);
    cudaGetSymbolAddress((void**)&Wkl,  g_Wkl);

    const int SMEM = 65536;
    cudaFuncSetAttribute(gemm_p<1,1>,   cudaFuncAttributeMaxDynamicSharedMemorySize, SMEM);
    cudaFuncSetAttribute(gemm_p<0,0>,   cudaFuncAttributeMaxDynamicSharedMemorySize, SMEM);
    cudaFuncSetAttribute(gemm_h<0,1,0>, cudaFuncAttributeMaxDynamicSharedMemorySize, SMEM);
    cudaFuncSetAttribute(gemm_h<1,0,0>, cudaFuncAttributeMaxDynamicSharedMemorySize, SMEM);
    cudaFuncSetAttribute(gemm_h<1,1,1>, cudaFuncAttributeMaxDynamicSharedMemorySize, SMEM);

    const int KW = EMBED / 2;                       // 512 words
    const size_t sQEw = (size_t)SEQ * KW;           // per-batch packed act stride
    const size_t sSS  = (size_t)SEQ * SEQ;          // per-batch score stride (f32)
    const size_t sSSw = sSS / 2;                    // per-batch attn words
    const size_t sVt  = (size_t)EMBED * (SEQ/2);    // per-batch V^T words

    // ---- pre-passes ----
    pack_src2<<<NROWS, 256>>>(src, Sh, Sl, SrcH);
    tpack_bf<<<dim3(16,16), 256>>>(Wq, Wqh, Wql, EMBED, EMBED);
    tpack_bf<<<dim3(16,16), 256>>>(Wk, Wkh, Wkl, EMBED, EMBED);
    tpack_h <<<dim3(16,16), 256>>>(Wv, WvtH, EMBED, EMBED, 0, 0);
    tpack_h <<<dim3(16,16), 256>>>(Wo, WotH, EMBED, EMBED, 0, 0);
    tpack_h <<<dim3(64,16), 256>>>(W1, W1tH, EMBED, DFF,   0, 0);
    tpack_h <<<dim3(16,64), 256>>>(W2, W2tH, DFF,   EMBED, 0, 0);

    // ---- Q, K projections (bf16 3-term, packed out) ----
    gemm_p<1,1><<<dim3(EMBED/128, NROWS/128), 256, SMEM>>>(Sh, Sl, Wqh, Wql, bq,
        nullptr, Qh, Ql, NROWS, EMBED, KW, 0, 0, 0);
    gemm_p<1,1><<<dim3(EMBED/128, NROWS/128), 256, SMEM>>>(Sh, Sl, Wkh, Wkl, bk,
        nullptr, Kh, Kl, NROWS, EMBED, KW, 0, 0, 0);

    // ---- V projection (fp16) -> f32, then transpose-pack per batch ----
    gemm_h<0,1,0><<<dim3(EMBED/128, NROWS/128), 256, SMEM>>>(SrcH, WvtH, bv,
        Vp, nullptr, NROWS, EMBED, KW, 0, 0, 0);
    tpack_h<<<dim3(16, 32, NBATCH), 256>>>(Vp, VtH, SEQ, EMBED,
        (size_t)SEQ * EMBED, sVt);

    // ---- scores = Q @ K^T (bf16 3-term) -> f32 ----
    gemm_p<0,0><<<dim3(SEQ/128, SEQ/128, NBATCH), 256, SMEM>>>(Qh, Ql, Kh, Kl, nullptr,
        S, nullptr, nullptr, SEQ, SEQ, KW, sQEw, sQEw, sSS);

    // ---- softmax -> packed fp16 attn ----
    softmax_kernel<<<NROWS, 256>>>(S, AtH);

    // ---- ao = attn @ V (fp16) -> packed ----
    gemm_h<1,0,0><<<dim3(EMBED/128, SEQ/128, NBATCH), 256, SMEM>>>(AtH, VtH, nullptr,
        nullptr, AoH, SEQ, EMBED, SEQ/2, sSSw, sVt, sQEw);

    // ---- out-proj (fp16) -> f32 ----
    gemm_h<0,1,0><<<dim3(EMBED/128, NROWS/128), 256, SMEM>>>(AoH, WotH, bo,
        AO, nullptr, NROWS, EMBED, KW, 0, 0, 0);

    add_ln_kernel<1><<<NROWS, 256>>>(src, AO, g1, be1, X, XH);

    // ---- ff1 = relu(x @ W1 + b1) (fp16) -> packed ----
    gemm_h<1,1,1><<<dim3(DFF/128, NROWS/128), 256, SMEM>>>(XH, W1tH, b1,
        nullptr, FH, NROWS, DFF, KW, 0, 0, 0);

    // ---- ff2 (fp16) -> f32 ----
    gemm_h<0,1,0><<<dim3(EMBED/128, NROWS/128), 256, SMEM>>>(FH, W2tH, b2,
        T, nullptr, NROWS, EMBED, DFF/2, 0, 0, 0);

    add_ln_kernel<0><<<NROWS, 256>>>(X, T, g2, be2, (float*)d_out, nullptr);
}

// round 12
// speedup vs baseline: 5.1776x; 1.1788x over previous
#include <cuda_runtime.h>
#include <cstdint>

#define EMBED 1024
#define DFF   4096
#define NBATCH 4
#define SEQ   2048
#define NROWS (NBATCH * SEQ)   // 8192

// ---------------- scratch (device globals: no allocations allowed) ----------
__device__ float    g_S   [(size_t)NBATCH * SEQ * SEQ];    // raw scores (f32)
__device__ float    g_T   [NROWS * EMBED];                 // ff2 out (f32)
__device__ float    g_AO  [NROWS * EMBED];                 // wo-gemm out (f32)
__device__ float    g_X   [NROWS * EMBED];                 // LN1 out f32 (residual)
__device__ float    g_Vp  [NROWS * EMBED];                 // V proj out (f32)
// fp16x2 packed operands (uint32 words = 2 halves, k-pairs)
__device__ __align__(16) uint32_t g_SrcH[NROWS * EMBED/2];
__device__ __align__(16) uint32_t g_XH  [NROWS * EMBED/2];
__device__ __align__(16) uint32_t g_AoH [NROWS * EMBED/2];
__device__ __align__(16) uint32_t g_FH  [(size_t)NROWS * DFF/2];
__device__ __align__(16) uint32_t g_AtH [(size_t)NBATCH * SEQ * SEQ/2];
__device__ __align__(16) uint32_t g_VtH [(size_t)NBATCH * EMBED * SEQ/2];
__device__ __align__(16) uint32_t g_WvtH[EMBED * EMBED/2];
__device__ __align__(16) uint32_t g_WotH[EMBED * EMBED/2];
__device__ __align__(16) uint32_t g_W1tH[(size_t)DFF * EMBED/2];
__device__ __align__(16) uint32_t g_W2tH[(size_t)EMBED * DFF/2];
// bf16 hi/lo packed (scores path)
__device__ __align__(16) uint32_t g_Sh [NROWS * EMBED/2], g_Sl [NROWS * EMBED/2];
__device__ __align__(16) uint32_t g_Qh [NROWS * EMBED/2], g_Ql [NROWS * EMBED/2];
__device__ __align__(16) uint32_t g_Kh [NROWS * EMBED/2], g_Kl [NROWS * EMBED/2];
__device__ __align__(16) uint32_t g_Wqh[EMBED * EMBED/2], g_Wql[EMBED * EMBED/2];
__device__ __align__(16) uint32_t g_Wkh[EMBED * EMBED/2], g_Wkl[EMBED * EMBED/2];

// ---------------- helpers ----------------------------------------------------
__device__ __forceinline__ uint32_t bfpack(float e0, float e1) {
    uint32_t d; asm("cvt.rn.bf16x2.f32 %0, %1, %2;" : "=r"(d) : "f"(e1), "f"(e0)); return d;
}
__device__ __forceinline__ uint32_t bfres(float e0, float e1, uint32_t h) {
    float h0 = __uint_as_float(h << 16);
    float h1 = __uint_as_float(h & 0xffff0000u);
    return bfpack(e0 - h0, e1 - h1);
}
__device__ __forceinline__ uint32_t hpack(float e0, float e1) {   // lo=e0, hi=e1
    uint32_t d; asm("cvt.rn.f16x2.f32 %0, %1, %2;" : "=r"(d) : "f"(e1), "f"(e0)); return d;
}

#define CP16(dst, src) \
    asm volatile("cp.async.cg.shared.global [%0], [%1], 16;" :: "r"(dst), "l"(src))
#define CP_COMMIT()  asm volatile("cp.async.commit_group;" ::: "memory")
#define CP_WAIT1()   asm volatile("cp.async.wait_group 1;" ::: "memory")
#define CP_WAIT0()   asm volatile("cp.async.wait_group 0;" ::: "memory")

#define LDSM4(r0, r1, r2, r3, addr) \
    asm volatile("ldmatrix.sync.aligned.m8n8.x4.shared.b16 {%0,%1,%2,%3}, [%4];" \
        : "=r"(r0), "=r"(r1), "=r"(r2), "=r"(r3) : "r"(addr))

#define MMA_BF16(d, A0, A1, A2, A3, B0, B1) \
    asm volatile("mma.sync.aligned.m16n8k16.row.col.f32.bf16.bf16.f32 " \
        "{%0,%1,%2,%3},{%4,%5,%6,%7},{%8,%9},{%0,%1,%2,%3};" \
        : "+f"((d)[0]), "+f"((d)[1]), "+f"((d)[2]), "+f"((d)[3]) \
        : "r"(A0), "r"(A1), "r"(A2), "r"(A3), "r"(B0), "r"(B1))

#define MMA_F16(d, A0, A1, A2, A3, B0, B1) \
    asm volatile("mma.sync.aligned.m16n8k16.row.col.f32.f16.f16.f32 " \
        "{%0,%1,%2,%3},{%4,%5,%6,%7},{%8,%9},{%0,%1,%2,%3};" \
        : "+f"((d)[0]), "+f"((d)[1]), "+f"((d)[2]), "+f"((d)[3]) \
        : "r"(A0), "r"(A1), "r"(A2), "r"(A3), "r"(B0), "r"(B1))

// ============================================================================
// gemm_p: bf16 hi/lo 3-term GEMM (scores path), LDSM fragment loads.
// A:[M][Kw] row pack (hi,lo separate in GMEM); B:[N][Kw] k-major pack.
// SMEM per stage: A rows 0..127 of 32 words (logical chunks: 0-3 = hi k-chunks,
// 4-7 = lo k-chunks; chunk L stored at ((L ^ (r&7))<<2 words), B at +4096 words.
// K-tile 32 k (2 k16 steps). 12 LDSM + 48 MMA per step.
// ============================================================================
template<int OUTPACK, int BIAS>
__global__ void __launch_bounds__(256, 1)
gemm_p(const uint32_t* __restrict__ Ah, const uint32_t* __restrict__ Al,
       const uint32_t* __restrict__ Bh, const uint32_t* __restrict__ Bl,
       const float* __restrict__ bias,
       float* __restrict__ C, uint32_t* __restrict__ Ch, uint32_t* __restrict__ Cl,
       int M, int N, int Kw,
       size_t sAw, size_t sBw, size_t sCe)
{
    Ah += (size_t)blockIdx.z * sAw;  Al += (size_t)blockIdx.z * sAw;
    Bh += (size_t)blockIdx.z * sBw;  Bl += (size_t)blockIdx.z * sBw;
    if (!OUTPACK) C += (size_t)blockIdx.z * sCe;

    extern __shared__ uint32_t smp[];
    const uint32_t smbase = (uint32_t)__cvta_generic_to_shared(smp);

    const int tid  = threadIdx.x;
    const int lane = tid & 31;
    const int wid  = tid >> 5;
    const int g    = lane >> 2;
    const int tig  = lane & 3;
    const int wm   = wid & 1;
    const int wn   = wid >> 1;
    const int row0 = blockIdx.y * 128;
    const int col0 = blockIdx.x * 128;
    const int nwB  = wn * 32;

    // LDSM addressing invariants
    const int aHi = lane >> 4;                                   // 0/1 -> k-chunk bit
    const int la15 = lane & 15;
    const int bHi = (lane >> 3) & 1;
    const int rbl = (lane & 7) + ((lane >> 4) << 3);             // B row-in-pair

    float acc[4][4][4];
#pragma unroll
    for (int mi = 0; mi < 4; mi++)
#pragma unroll
        for (int ni = 0; ni < 4; ni++)
#pragma unroll
            for (int j = 0; j < 4; j++) acc[mi][ni][j] = 0.f;

    auto issue = [&](int ktw, int s) {
        const uint32_t base = smbase + s * (8192 * 4);
        const uint32_t* gp[4] = { Ah, Al, Bh, Bl };
#pragma unroll
        for (int i = 0; i < 8; i++) {
            int flat = i * 256 + tid;          // 0..2047
            int a    = flat >> 9;              // array 0..3
            int rem  = flat & 511;
            int r    = rem >> 2;               // row 0..127
            int c    = rem & 3;                // k-chunk 0..3
            const int ro = (a < 2) ? row0 : col0;
            const uint32_t* src = gp[a] + (size_t)(ro + r) * Kw + ktw + c * 4;
            const int L = (a & 1) ? (c ^ 4) : c;          // lo arrays -> chunks 4-7
            const uint32_t side = (a < 2) ? 0u : 4096u * 4u;
            uint32_t dst = base + side + (r * 32 + ((L ^ (r & 7)) << 2)) * 4;
            CP16(dst, src);
        }
        CP_COMMIT();
    };

    auto compute = [&](int s) {
        const uint32_t sA = smbase + s * (8192 * 4);
        const uint32_t sB = sA + 4096 * 4;
#pragma unroll
        for (int ks = 0; ks < 2; ks++) {
            uint32_t ah[4][4], al[4][4];
#pragma unroll
            for (int mi = 0; mi < 4; mi++) {
                const int ra = wm * 64 + mi * 16 + la15;
                const uint32_t rbase = sA + ra * 128;
                const int ch = 2 * ks + aHi;
                LDSM4(ah[mi][0], ah[mi][1], ah[mi][2], ah[mi][3],
                      rbase + ((ch ^ (ra & 7)) << 4));
                LDSM4(al[mi][0], al[mi][1], al[mi][2], al[mi][3],
                      rbase + (((ch ^ 4) ^ (ra & 7)) << 4));
            }
#pragma unroll
            for (int p = 0; p < 2; p++) {
                const int rb = nwB + p * 16 + rbl;
                const uint32_t rbase = sB + rb * 128;
                const int ch = 2 * ks + bHi;
                uint32_t bh0, bh1, bh2, bh3, bl0, bl1, bl2, bl3;
                LDSM4(bh0, bh1, bh2, bh3, rbase + ((ch ^ (rb & 7)) << 4));
                LDSM4(bl0, bl1, bl2, bl3, rbase + (((ch ^ 4) ^ (rb & 7)) << 4));
#pragma unroll
                for (int mi = 0; mi < 4; mi++) {
                    MMA_BF16(acc[mi][2*p],   ah[mi][0], ah[mi][1], ah[mi][2], ah[mi][3], bh0, bh1);
                    MMA_BF16(acc[mi][2*p+1], ah[mi][0], ah[mi][1], ah[mi][2], ah[mi][3], bh2, bh3);
                }
#pragma unroll
                for (int mi = 0; mi < 4; mi++) {
                    MMA_BF16(acc[mi][2*p],   al[mi][0], al[mi][1], al[mi][2], al[mi][3], bh0, bh1);
                    MMA_BF16(acc[mi][2*p+1], al[mi][0], al[mi][1], al[mi][2], al[mi][3], bh2, bh3);
                }
#pragma unroll
                for (int mi = 0; mi < 4; mi++) {
                    MMA_BF16(acc[mi][2*p],   ah[mi][0], ah[mi][1], ah[mi][2], ah[mi][3], bl0, bl1);
                    MMA_BF16(acc[mi][2*p+1], ah[mi][0], ah[mi][1], ah[mi][2], ah[mi][3], bl2, bl3);
                }
            }
        }
    };

    const int ktiles = Kw / 16;
    issue(0, 0);
    for (int t = 0; t < ktiles; t++) {
        if (t + 1 < ktiles) { issue((t + 1) * 16, (t + 1) & 1); CP_WAIT1(); }
        else                { CP_WAIT0(); }
        __syncthreads();
        compute(t & 1);
        __syncthreads();
    }

#pragma unroll
    for (int mi = 0; mi < 4; mi++) {
        const int r0 = row0 + wm * 64 + mi * 16 + g;
#pragma unroll
        for (int ni = 0; ni < 4; ni++) {
            const int c = col0 + nwB + ni * 8 + tig * 2;
            float f0 = acc[mi][ni][0], f1 = acc[mi][ni][1];
            float f2 = acc[mi][ni][2], f3 = acc[mi][ni][3];
            if (BIAS) {
                const float2 bb = *(const float2*)&bias[c];
                f0 += bb.x; f1 += bb.y; f2 += bb.x; f3 += bb.y;
            }
            if (OUTPACK) {
                const int Nw = N >> 1, wc = c >> 1;
                uint32_t h0 = bfpack(f0, f1), h1 = bfpack(f2, f3);
                Ch[(size_t)r0 * Nw + wc]       = h0;
                Cl[(size_t)r0 * Nw + wc]       = bfres(f0, f1, h0);
                Ch[(size_t)(r0 + 8) * Nw + wc] = h1;
                Cl[(size_t)(r0 + 8) * Nw + wc] = bfres(f2, f3, h1);
            } else {
                *(float2*)&C[(size_t)r0 * N + c]       = make_float2(f0, f1);
                *(float2*)&C[(size_t)(r0 + 8) * N + c] = make_float2(f2, f3);
            }
        }
    }
}

// ============================================================================
// gemm_h: plain fp16 GEMM, LDSM fragment loads.
// A:[M][Kw] row pack; B:[N][Kw] k-major pack (C = A·B^T over k).
// Block tile 128x128x(64 k = 32 words); SMEM layout unchanged from R11:
// word w of row r at r*32 + ((w>>2)^(r&7))*4 + (w&3). 6 LDSM + 16 MMA per k16.
// ============================================================================
template<int OUTPACK, int BIAS, int RELU>
__global__ void __launch_bounds__(256, 2)
gemm_h(const uint32_t* __restrict__ A, const uint32_t* __restrict__ B,
       const float* __restrict__ bias,
       float* __restrict__ C, uint32_t* __restrict__ Cp,
       int M, int N, int Kw,
       size_t sAw, size_t sBw, size_t sCo)
{
    A += (size_t)blockIdx.z * sAw;
    B += (size_t)blockIdx.z * sBw;
    if (OUTPACK) Cp += (size_t)blockIdx.z * sCo;
    else         C  += (size_t)blockIdx.z * sCo;

    extern __shared__ uint32_t smh[];   // 2 bufs x (A 4096 + B 4096) words = 64KB
    const uint32_t smbase = (uint32_t)__cvta_generic_to_shared(smh);

    const int tid  = threadIdx.x;
    const int lane = tid & 31;
    const int wid  = tid >> 5;
    const int g    = lane >> 2;
    const int tig  = lane & 3;
    const int wm   = wid & 1;
    const int wn   = wid >> 1;
    const int row0 = blockIdx.y * 128;
    const int col0 = blockIdx.x * 128;
    const int nwB  = wn * 32;

    const int aHi  = lane >> 4;
    const int la15 = lane & 15;
    const int bHi  = (lane >> 3) & 1;
    const int rbl  = (lane & 7) + ((lane >> 4) << 3);

    float acc[4][4][4];
#pragma unroll
    for (int mi = 0; mi < 4; mi++)
#pragma unroll
        for (int ni = 0; ni < 4; ni++)
#pragma unroll
            for (int j = 0; j < 4; j++) acc[mi][ni][j] = 0.f;

    auto issue = [&](int ktw, int s) {
        const uint32_t sa = smbase + s * (8192 * 4);
        const uint32_t sb = sa + 4096 * 4;
#pragma unroll
        for (int i = 0; i < 4; i++) {                 // A: 128 rows x 8 chunks
            int flat = i * 256 + tid;
            int r = flat >> 3, c = flat & 7;
            const uint32_t* src = A + (size_t)(row0 + r) * Kw + ktw + c * 4;
            uint32_t dst = sa + (r * 32 + ((c ^ (r & 7)) << 2)) * 4;
            CP16(dst, src);
        }
#pragma unroll
        for (int i = 0; i < 4; i++) {                 // B: 128 rows x 8 chunks
            int flat = i * 256 + tid;
            int r = flat >> 3, c = flat & 7;
            const uint32_t* src = B + (size_t)(col0 + r) * Kw + ktw + c * 4;
            uint32_t dst = sb + (r * 32 + ((c ^ (r & 7)) << 2)) * 4;
            CP16(dst, src);
        }
        CP_COMMIT();
    };

    auto compute = [&](int s) {
        const uint32_t sA = smbase + s * (8192 * 4);
        const uint32_t sB = sA + 4096 * 4;
#pragma unroll
        for (int ks = 0; ks < 4; ks++) {
            uint32_t a[4][4];
#pragma unroll
            for (int mi = 0; mi < 4; mi++) {
                const int ra = wm * 64 + mi * 16 + la15;
                LDSM4(a[mi][0], a[mi][1], a[mi][2], a[mi][3],
                      sA + ra * 128 + (((2 * ks + aHi) ^ (ra & 7)) << 4));
            }
#pragma unroll
            for (int p = 0; p < 2; p++) {
                const int rb = nwB + p * 16 + rbl;
                uint32_t b0, b1, b2, b3;
                LDSM4(b0, b1, b2, b3,
                      sB + rb * 128 + (((2 * ks + bHi) ^ (rb & 7)) << 4));
#pragma unroll
                for (int mi = 0; mi < 4; mi++) {
                    MMA_F16(acc[mi][2*p],   a[mi][0], a[mi][1], a[mi][2], a[mi][3], b0, b1);
                    MMA_F16(acc[mi][2*p+1], a[mi][0], a[mi][1], a[mi][2], a[mi][3], b2, b3);
                }
            }
        }
    };

    const int ktiles = Kw / 32;
    issue(0, 0);
    for (int t = 0; t < ktiles; t++) {
        if (t + 1 < ktiles) { issue((t + 1) * 32, (t + 1) & 1); CP_WAIT1(); }
        else                { CP_WAIT0(); }
        __syncthreads();
        compute(t & 1);
        __syncthreads();
    }

#pragma unroll
    for (int mi = 0; mi < 4; mi++) {
        const int r0 = row0 + wm * 64 + mi * 16 + g;
#pragma unroll
        for (int ni = 0; ni < 4; ni++) {
            const int c = col0 + nwB + ni * 8 + tig * 2;
            float f0 = acc[mi][ni][0], f1 = acc[mi][ni][1];
            float f2 = acc[mi][ni][2], f3 = acc[mi][ni][3];
            if (BIAS) {
                const float2 bb = *(const float2*)&bias[c];
                f0 += bb.x; f1 += bb.y; f2 += bb.x; f3 += bb.y;
            }
            if (RELU) {
                f0 = fmaxf(f0, 0.f); f1 = fmaxf(f1, 0.f);
                f2 = fmaxf(f2, 0.f); f3 = fmaxf(f3, 0.f);
            }
            if (OUTPACK) {
                const int Nw = N >> 1, wc = c >> 1;
                Cp[(size_t)r0 * Nw + wc]       = hpack(f0, f1);
                Cp[(size_t)(r0 + 8) * Nw + wc] = hpack(f2, f3);
            } else {
                *(float2*)&C[(size_t)r0 * N + c]       = make_float2(f0, f1);
                *(float2*)&C[(size_t)(r0 + 8) * N + c] = make_float2(f2, f3);
            }
        }
    }
}

// ---------------- pre-pass kernels ------------------------------------------
__global__ void pack_src2(const float* __restrict__ src,
                          uint32_t* __restrict__ Sh, uint32_t* __restrict__ Sl,
                          uint32_t* __restrict__ SrcH)
{
    const size_t row = blockIdx.x;
    const int t = threadIdx.x;
#pragma unroll
    for (int j = 0; j < 2; j++) {
        const int p = t + j * 256;
        const float2 v = *(const float2*)(src + row * EMBED + 2 * p);
        uint32_t h = bfpack(v.x, v.y);
        Sh[row * (EMBED/2) + p] = h;
        Sl[row * (EMBED/2) + p] = bfres(v.x, v.y, h);
        SrcH[row * (EMBED/2) + p] = hpack(v.x, v.y);
    }
}

// tiled transpose-pack: A[K x N] f32 -> At[N][K/2] fp16x2 (scalar tile stores)
__global__ void tpack_h(const float* __restrict__ A, uint32_t* __restrict__ At,
                        int K, int N, size_t sA, size_t sAt)
{
    A  += (size_t)blockIdx.z * sA;
    At += (size_t)blockIdx.z * sAt;
    __shared__ float tile[64][65];
    const int k0 = blockIdx.y * 64, n0 = blockIdx.x * 64;
    const int t = threadIdx.x;
#pragma unroll
    for (int i = 0; i < 4; i++) {
        int flat = i * 256 + t;
        int r = flat >> 4, c = (flat & 15) * 4;
        float4 v = *(const float4*)(A + (size_t)(k0 + r) * N + n0 + c);
        tile[r][c]     = v.x;
        tile[r][c + 1] = v.y;
        tile[r][c + 2] = v.z;
        tile[r][c + 3] = v.w;
    }
    __syncthreads();
#pragma unroll
    for (int i = 0; i < 8; i++) {
        int flat = i * 256 + t;
        int n = flat >> 5, w = flat & 31;
        At[(size_t)(n0 + n) * (K >> 1) + (k0 >> 1) + w] =
            hpack(tile[2 * w][n], tile[2 * w + 1][n]);
    }
}

// tiled transpose-pack: W[K x N] f32 -> Wh/Wl[N][K/2] bf16 hi/lo
__global__ void tpack_bf(const float* __restrict__ W,
                         uint32_t* __restrict__ Wh, uint32_t* __restrict__ Wl,
                         int K, int N)
{
    __shared__ float tile[64][65];
    const int k0 = blockIdx.y * 64, n0 = blockIdx.x * 64;
    const int t = threadIdx.x;
#pragma unroll
    for (int i = 0; i < 4; i++) {
        int flat = i * 256 + t;
        int r = flat >> 4, c = (flat & 15) * 4;
        float4 v = *(const float4*)(W + (size_t)(k0 + r) * N + n0 + c);
        tile[r][c]     = v.x;
        tile[r][c + 1] = v.y;
        tile[r][c + 2] = v.z;
        tile[r][c + 3] = v.w;
    }
    __syncthreads();
#pragma unroll
    for (int i = 0; i < 8; i++) {
        int flat = i * 256 + t;
        int n = flat >> 5, w = flat & 31;
        float e0 = tile[2 * w][n], e1 = tile[2 * w + 1][n];
        uint32_t h = bfpack(e0, e1);
        Wh[(size_t)(n0 + n) * (K >> 1) + (k0 >> 1) + w] = h;
        Wl[(size_t)(n0 + n) * (K >> 1) + (k0 >> 1) + w] = bfres(e0, e1, h);
    }
}

// ---------------- softmax: read raw scores, emit packed fp16 attn ------------
__global__ void softmax_kernel(const float* __restrict__ S, uint32_t* __restrict__ AtH)
{
    const float* p = S + (size_t)blockIdx.x * SEQ;
    uint32_t* q = AtH + (size_t)blockIdx.x * (SEQ/2);
    const int tid  = threadIdx.x;     // 256 threads
    const int lane = tid & 31;
    const int warp = tid >> 5;

    float4 v0 = ((const float4*)p)[tid];
    float4 v1 = ((const float4*)p)[tid + 256];

    __shared__ float sh[8];

    float m = fmaxf(fmaxf(fmaxf(v0.x, v0.y), fmaxf(v0.z, v0.w)),
                    fmaxf(fmaxf(v1.x, v1.y), fmaxf(v1.z, v1.w)));
#pragma unroll
    for (int o = 16; o > 0; o >>= 1) m = fmaxf(m, __shfl_xor_sync(0xffffffffu, m, o));
    if (lane == 0) sh[warp] = m;
    __syncthreads();
    if (tid < 32) {
        float t = (tid < 8) ? sh[tid] : -3.402823e38f;
#pragma unroll
        for (int o = 4; o > 0; o >>= 1) t = fmaxf(t, __shfl_xor_sync(0xffffffffu, t, o));
        if (tid == 0) sh[0] = t;
    }
    __syncthreads();
    m = sh[0];
    __syncthreads();

    v0.x = __expf(v0.x - m); v0.y = __expf(v0.y - m);
    v0.z = __expf(v0.z - m); v0.w = __expf(v0.w - m);
    v1.x = __expf(v1.x - m); v1.y = __expf(v1.y - m);
    v1.z = __expf(v1.z - m); v1.w = __expf(v1.w - m);

    float s = v0.x + v0.y + v0.z + v0.w + v1.x + v1.y + v1.z + v1.w;
#pragma unroll
    for (int o = 16; o > 0; o >>= 1) s += __shfl_xor_sync(0xffffffffu, s, o);
    if (lane == 0) sh[warp] = s;
    __syncthreads();
    if (tid < 32) {
        float t = (tid < 8) ? sh[tid] : 0.f;
#pragma unroll
        for (int o = 4; o > 0; o >>= 1) t += __shfl_xor_sync(0xffffffffu, t, o);
        if (tid == 0) sh[0] = t;
    }
    __syncthreads();
    const float r = 1.f / sh[0];

    q[2*tid]           = hpack(v0.x * r, v0.y * r);
    q[2*tid + 1]       = hpack(v0.z * r, v0.w * r);
    q[512 + 2*tid]     = hpack(v1.x * r, v1.y * r);
    q[512 + 2*tid + 1] = hpack(v1.z * r, v1.w * r);
}

// ---------------- residual + layernorm: O = LN(X+Y)*g + b [, OH = fp16(O)] --
template<int WR>
__global__ void add_ln_kernel(const float* __restrict__ X, const float* __restrict__ Y,
                              const float* __restrict__ g, const float* __restrict__ b,
                              float* __restrict__ O, uint32_t* __restrict__ OH)
{
    const size_t row = blockIdx.x;
    const int tid  = threadIdx.x;   // 256 threads
    const int lane = tid & 31;
    const int warp = tid >> 5;

    const float4 x = ((const float4*)(X + row * EMBED))[tid];
    const float4 y = ((const float4*)(Y + row * EMBED))[tid];
    float4 v;
    v.x = x.x + y.x; v.y = x.y + y.y; v.z = x.z + y.z; v.w = x.w + y.w;

    float s1 = v.x + v.y + v.z + v.w;
    float s2 = v.x * v.x + v.y * v.y + v.z * v.z + v.w * v.w;

    __shared__ float sh1[8], sh2[8];
#pragma unroll
    for (int o = 16; o > 0; o >>= 1) {
        s1 += __shfl_xor_sync(0xffffffffu, s1, o);
        s2 += __shfl_xor_sync(0xffffffffu, s2, o);
    }
    if (lane == 0) { sh1[warp] = s1; sh2[warp] = s2; }
    __syncthreads();
    if (tid < 32) {
        float t1 = (tid < 8) ? sh1[tid] : 0.f;
        float t2 = (tid < 8) ? sh2[tid] : 0.f;
#pragma unroll
        for (int o = 4; o > 0; o >>= 1) {
            t1 += __shfl_xor_sync(0xffffffffu, t1, o);
            t2 += __shfl_xor_sync(0xffffffffu, t2, o);
        }
        if (tid == 0) { sh1[0] = t1; sh2[0] = t2; }
    }
    __syncthreads();

    const float inv = 1.f / (float)EMBED;
    const float mu  = sh1[0] * inv;
    const float var = sh2[0] * inv - mu * mu;
    const float r   = rsqrtf(var + 1e-5f);

    const float4 gg = ((const float4*)g)[tid];
    const float4 bb = ((const float4*)b)[tid];
    float4 o;
    o.x = (v.x - mu) * r * gg.x + bb.x;
    o.y = (v.y - mu) * r * gg.y + bb.y;
    o.z = (v.z - mu) * r * gg.z + bb.z;
    o.w = (v.w - mu) * r * gg.w + bb.w;
    ((float4*)(O + row * EMBED))[tid] = o;
    if (WR) {
        OH[row * (EMBED/2) + 2*tid]     = hpack(o.x, o.y);
        OH[row * (EMBED/2) + 2*tid + 1] = hpack(o.z, o.w);
    }
}

// ---------------- launch -----------------------------------------------------
extern "C" void kernel_launch(void* const* d_in, const int* in_sizes, int n_in,
                              void* d_out, int out_size)
{
    const float* src = (const float*)d_in[0];
    const float* Wq  = (const float*)d_in[1];
    const float* bq  = (const float*)d_in[2];
    const float* Wk  = (const float*)d_in[3];
    const float* bk  = (const float*)d_in[4];
    const float* Wv  = (const float*)d_in[5];
    const float* bv  = (const float*)d_in[6];
    const float* Wo  = (const float*)d_in[7];
    const float* bo  = (const float*)d_in[8];
    const float* W1  = (const float*)d_in[9];
    const float* b1  = (const float*)d_in[10];
    const float* W2  = (const float*)d_in[11];
    const float* b2  = (const float*)d_in[12];
    const float* g1  = (const float*)d_in[13];
    const float* be1 = (const float*)d_in[14];
    const float* g2  = (const float*)d_in[15];
    const float* be2 = (const float*)d_in[16];

    float *S, *T, *AO, *X, *Vp;
    uint32_t *SrcH, *XH, *AoH, *FH, *AtH, *VtH, *WvtH, *WotH, *W1tH, *W2tH;
    uint32_t *Sh, *Sl, *Qh, *Ql, *Kh, *Kl, *Wqh, *Wql, *Wkh, *Wkl;
    cudaGetSymbolAddress((void**)&S,    g_S);
    cudaGetSymbolAddress((void**)&T,    g_T);
    cudaGetSymbolAddress((void**)&AO,   g_AO);
    cudaGetSymbolAddress((void**)&X,    g_X);
    cudaGetSymbolAddress((void**)&Vp,   g_Vp);
    cudaGetSymbolAddress((void**)&SrcH, g_SrcH);
    cudaGetSymbolAddress((void**)&XH,   g_XH);
    cudaGetSymbolAddress((void**)&AoH,  g_AoH);
    cudaGetSymbolAddress((void**)&FH,   g_FH);
    cudaGetSymbolAddress((void**)&AtH,  g_AtH);
    cudaGetSymbolAddress((void**)&VtH,  g_VtH);
    cudaGetSymbolAddress((void**)&WvtH, g_WvtH);
    cudaGetSymbolAddress((void**)&WotH, g_WotH);
    cudaGetSymbolAddress((void**)&W1tH, g_W1tH);
    cudaGetSymbolAddress((void**)&W2tH, g_W2tH);
    cudaGetSymbolAddress((void**)&Sh,   g_Sh);
    cudaGetSymbolAddress((void**)&Sl,   g_Sl);
    cudaGetSymbolAddress((void**)&Qh,   g_Qh);
    cudaGetSymbolAddress((void**)&Ql,   g_Ql);
    cudaGetSymbolAddress((void**)&Kh,   g_Kh);
    cudaGetSymbolAddress((void**)&Kl,   g_Kl);
    cudaGetSymbolAddress((void**)&Wqh,  g_Wqh);
    cudaGetSymbolAddress((void**)&Wql,  g_Wql);
    cudaGetSymbolAddress((void**)&Wkh,  g_Wkh);
    cudaGetSymbolAddress((void**)&Wkl,  g_Wkl);

    const int SMEM = 65536;
    cudaFuncSetAttribute(gemm_p<1,1>,   cudaFuncAttributeMaxDynamicSharedMemorySize, SMEM);
    cudaFuncSetAttribute(gemm_p<0,0>,   cudaFuncAttributeMaxDynamicSharedMemorySize, SMEM);
    cudaFuncSetAttribute(gemm_h<0,1,0>, cudaFuncAttributeMaxDynamicSharedMemorySize, SMEM);
    cudaFuncSetAttribute(gemm_h<1,0,0>, cudaFuncAttributeMaxDynamicSharedMemorySize, SMEM);
    cudaFuncSetAttribute(gemm_h<1,1,1>, cudaFuncAttributeMaxDynamicSharedMemorySize, SMEM);

    const int KW = EMBED / 2;                       // 512 words
    const size_t sQEw = (size_t)SEQ * KW;           // per-batch packed act stride
    const size_t sSS  = (size_t)SEQ * SEQ;          // per-batch score stride (f32)
    const size_t sSSw = sSS / 2;                    // per-batch attn words
    const size_t sVt  = (size_t)EMBED * (SEQ/2);    // per-batch V^T words

    // launch order arranged so launch #4 (ncu capture slot) = gemm_h V-proj
    pack_src2<<<NROWS, 256>>>(src, Sh, Sl, SrcH);                       // 1
    tpack_h <<<dim3(16,16), 256>>>(Wv, WvtH, EMBED, EMBED, 0, 0);       // 2
    tpack_bf<<<dim3(16,16), 256>>>(Wq, Wqh, Wql, EMBED, EMBED);         // 3
    gemm_h<0,1,0><<<dim3(EMBED/128, NROWS/128), 256, SMEM>>>(SrcH, WvtH, bv,
        Vp, nullptr, NROWS, EMBED, KW, 0, 0, 0);                        // 4 <- profiled
    tpack_bf<<<dim3(16,16), 256>>>(Wk, Wkh, Wkl, EMBED, EMBED);         // 5
    tpack_h <<<dim3(16,16), 256>>>(Wo, WotH, EMBED, EMBED, 0, 0);
    tpack_h <<<dim3(64,16), 256>>>(W1, W1tH, EMBED, DFF,   0, 0);
    tpack_h <<<dim3(16,64), 256>>>(W2, W2tH, DFF,   EMBED, 0, 0);

    // Q, K projections (bf16 3-term, packed out)
    gemm_p<1,1><<<dim3(EMBED/128, NROWS/128), 256, SMEM>>>(Sh, Sl, Wqh, Wql, bq,
        nullptr, Qh, Ql, NROWS, EMBED, KW, 0, 0, 0);
    gemm_p<1,1><<<dim3(EMBED/128, NROWS/128), 256, SMEM>>>(Sh, Sl, Wkh, Wkl, bk,
        nullptr, Kh, Kl, NROWS, EMBED, KW, 0, 0, 0);

    // V^T pack per batch
    tpack_h<<<dim3(16, 32, NBATCH), 256>>>(Vp, VtH, SEQ, EMBED,
        (size_t)SEQ * EMBED, sVt);

    // scores = Q @ K^T (bf16 3-term) -> f32
    gemm_p<0,0><<<dim3(SEQ/128, SEQ/128, NBATCH), 256, SMEM>>>(Qh, Ql, Kh, Kl, nullptr,
        S, nullptr, nullptr, SEQ, SEQ, KW, sQEw, sQEw, sSS);

    // softmax -> packed fp16 attn
    softmax_kernel<<<NROWS, 256>>>(S, AtH);

    // ao = attn @ V (fp16) -> packed
    gemm_h<1,0,0><<<dim3(EMBED/128, SEQ/128, NBATCH), 256, SMEM>>>(AtH, VtH, nullptr,
        nullptr, AoH, SEQ, EMBED, SEQ/2, sSSw, sVt, sQEw);

    // out-proj (fp16) -> f32
    gemm_h<0,1,0><<<dim3(EMBED/128, NROWS/128), 256, SMEM>>>(AoH, WotH, bo,
        AO, nullptr, NROWS, EMBED, KW, 0, 0, 0);

    add_ln_kernel<1><<<NROWS, 256>>>(src, AO, g1, be1, X, XH);

    // ff1 = relu(x @ W1 + b1) (fp16) -> packed
    gemm_h<1,1,1><<<dim3(DFF/128, NROWS/128), 256, SMEM>>>(XH, W1tH, b1,
        nullptr, FH, NROWS, DFF, KW, 0, 0, 0);

    // ff2 (fp16) -> f32
    gemm_h<0,1,0><<<dim3(EMBED/128, NROWS/128), 256, SMEM>>>(FH, W2tH, b2,
        T, nullptr, NROWS, EMBED, DFF/2, 0, 0, 0);

    add_ln_kernel<0><<<NROWS, 256>>>(X, T, g2, be2, (float*)d_out, nullptr);
}

// round 13
// speedup vs baseline: 5.4378x; 1.0502x over previous
#include <cuda_runtime.h>
#include <cstdint>

#define EMBED 1024
#define DFF   4096
#define NBATCH 4
#define SEQ   2048
#define NROWS (NBATCH * SEQ)   // 8192

// ---------------- scratch (device globals: no allocations allowed) ----------
__device__ float    g_S   [(size_t)NBATCH * SEQ * SEQ];    // raw scores (f32)
__device__ float    g_T   [NROWS * EMBED];                 // ff2 out (f32)
__device__ float    g_AO  [NROWS * EMBED];                 // wo-gemm out (f32)
__device__ float    g_X   [NROWS * EMBED];                 // LN1 out f32 (residual)
__device__ float    g_Vp  [NROWS * EMBED];                 // V proj out (f32)
// fp16x2 packed operands (uint32 words = 2 halves, k-pairs)
__device__ __align__(16) uint32_t g_SrcH[NROWS * EMBED/2];
__device__ __align__(16) uint32_t g_XH  [NROWS * EMBED/2];
__device__ __align__(16) uint32_t g_AoH [NROWS * EMBED/2];
__device__ __align__(16) uint32_t g_FH  [(size_t)NROWS * DFF/2];
__device__ __align__(16) uint32_t g_AtH [(size_t)NBATCH * SEQ * SEQ/2];
__device__ __align__(16) uint32_t g_VtH [(size_t)NBATCH * EMBED * SEQ/2];
__device__ __align__(16) uint32_t g_WvtH[EMBED * EMBED/2];
__device__ __align__(16) uint32_t g_WotH[EMBED * EMBED/2];
__device__ __align__(16) uint32_t g_W1tH[(size_t)DFF * EMBED/2];
__device__ __align__(16) uint32_t g_W2tH[(size_t)EMBED * DFF/2];
// bf16 hi/lo packed (scores path)
__device__ __align__(16) uint32_t g_Sh [NROWS * EMBED/2], g_Sl [NROWS * EMBED/2];
__device__ __align__(16) uint32_t g_Qh [NROWS * EMBED/2], g_Ql [NROWS * EMBED/2];
__device__ __align__(16) uint32_t g_Kh [NROWS * EMBED/2], g_Kl [NROWS * EMBED/2];
__device__ __align__(16) uint32_t g_Wqh[EMBED * EMBED/2], g_Wql[EMBED * EMBED/2];
__device__ __align__(16) uint32_t g_Wkh[EMBED * EMBED/2], g_Wkl[EMBED * EMBED/2];

// ---------------- helpers ----------------------------------------------------
__device__ __forceinline__ uint32_t bfpack(float e0, float e1) {
    uint32_t d; asm("cvt.rn.bf16x2.f32 %0, %1, %2;" : "=r"(d) : "f"(e1), "f"(e0)); return d;
}
__device__ __forceinline__ uint32_t bfres(float e0, float e1, uint32_t h) {
    float h0 = __uint_as_float(h << 16);
    float h1 = __uint_as_float(h & 0xffff0000u);
    return bfpack(e0 - h0, e1 - h1);
}
__device__ __forceinline__ uint32_t hpack(float e0, float e1) {   // lo=e0, hi=e1
    uint32_t d; asm("cvt.rn.f16x2.f32 %0, %1, %2;" : "=r"(d) : "f"(e1), "f"(e0)); return d;
}

#define CP16(dst, src) \
    asm volatile("cp.async.cg.shared.global [%0], [%1], 16;" :: "r"(dst), "l"(src))
#define CP_COMMIT()  asm volatile("cp.async.commit_group;" ::: "memory")
#define CP_WAIT1()   asm volatile("cp.async.wait_group 1;" ::: "memory")
#define CP_WAIT0()   asm volatile("cp.async.wait_group 0;" ::: "memory")

#define LDSM4(r0, r1, r2, r3, addr) \
    asm volatile("ldmatrix.sync.aligned.m8n8.x4.shared.b16 {%0,%1,%2,%3}, [%4];" \
        : "=r"(r0), "=r"(r1), "=r"(r2), "=r"(r3) : "r"(addr))

#define MMA_BF16(d, A0, A1, A2, A3, B0, B1) \
    asm volatile("mma.sync.aligned.m16n8k16.row.col.f32.bf16.bf16.f32 " \
        "{%0,%1,%2,%3},{%4,%5,%6,%7},{%8,%9},{%0,%1,%2,%3};" \
        : "+f"((d)[0]), "+f"((d)[1]), "+f"((d)[2]), "+f"((d)[3]) \
        : "r"(A0), "r"(A1), "r"(A2), "r"(A3), "r"(B0), "r"(B1))

#define MMA_F16(d, A0, A1, A2, A3, B0, B1) \
    asm volatile("mma.sync.aligned.m16n8k16.row.col.f32.f16.f16.f32 " \
        "{%0,%1,%2,%3},{%4,%5,%6,%7},{%8,%9},{%0,%1,%2,%3};" \
        : "+f"((d)[0]), "+f"((d)[1]), "+f"((d)[2]), "+f"((d)[3]) \
        : "r"(A0), "r"(A1), "r"(A2), "r"(A3), "r"(B0), "r"(B1))

// ============================================================================
// gemm_p: bf16 hi/lo 3-term GEMM (scores path), LDSM loads, 3-stage pipeline.
// A:[M][Kw] row pack (hi,lo separate in GMEM); B:[N][Kw] k-major pack.
// SMEM stage: A rows of 32 words (chunks 0-3 = hi, 4-7 = lo; chunk L at
// ((L^(r&7))<<2)), B at +4096 words. One __syncthreads per k-tile.
// ============================================================================
template<int OUTPACK, int BIAS>
__global__ void __launch_bounds__(256, 1)
gemm_p(const uint32_t* __restrict__ Ah, const uint32_t* __restrict__ Al,
       const uint32_t* __restrict__ Bh, const uint32_t* __restrict__ Bl,
       const float* __restrict__ bias,
       float* __restrict__ C, uint32_t* __restrict__ Ch, uint32_t* __restrict__ Cl,
       int M, int N, int Kw,
       size_t sAw, size_t sBw, size_t sCe)
{
    Ah += (size_t)blockIdx.z * sAw;  Al += (size_t)blockIdx.z * sAw;
    Bh += (size_t)blockIdx.z * sBw;  Bl += (size_t)blockIdx.z * sBw;
    if (!OUTPACK) C += (size_t)blockIdx.z * sCe;

    extern __shared__ uint32_t smp[];
    const uint32_t smbase = (uint32_t)__cvta_generic_to_shared(smp);

    const int tid  = threadIdx.x;
    const int lane = tid & 31;
    const int wid  = tid >> 5;
    const int g    = lane >> 2;
    const int tig  = lane & 3;
    const int wm   = wid & 1;
    const int wn   = wid >> 1;
    const int row0 = blockIdx.y * 128;
    const int col0 = blockIdx.x * 128;
    const int nwB  = wn * 32;

    const int aHi  = lane >> 4;
    const int la15 = lane & 15;
    const int bHi  = (lane >> 3) & 1;
    const int rbl  = (lane & 7) + ((lane >> 4) << 3);

    float acc[4][4][4];
#pragma unroll
    for (int mi = 0; mi < 4; mi++)
#pragma unroll
        for (int ni = 0; ni < 4; ni++)
#pragma unroll
            for (int j = 0; j < 4; j++) acc[mi][ni][j] = 0.f;

    auto issue = [&](int ktw, int s) {
        const uint32_t base = smbase + s * (8192 * 4);
        const uint32_t* gp[4] = { Ah, Al, Bh, Bl };
#pragma unroll
        for (int i = 0; i < 8; i++) {
            int flat = i * 256 + tid;          // 0..2047
            int a    = flat >> 9;              // array 0..3
            int rem  = flat & 511;
            int r    = rem >> 2;               // row 0..127
            int c    = rem & 3;                // k-chunk 0..3
            const int ro = (a < 2) ? row0 : col0;
            const uint32_t* src = gp[a] + (size_t)(ro + r) * Kw + ktw + c * 4;
            const int L = (a & 1) ? (c ^ 4) : c;          // lo arrays -> chunks 4-7
            const uint32_t side = (a < 2) ? 0u : 4096u * 4u;
            uint32_t dst = base + side + (r * 32 + ((L ^ (r & 7)) << 2)) * 4;
            CP16(dst, src);
        }
        CP_COMMIT();
    };

    auto compute = [&](int s) {
        const uint32_t sA = smbase + s * (8192 * 4);
        const uint32_t sB = sA + 4096 * 4;
#pragma unroll
        for (int ks = 0; ks < 2; ks++) {
            uint32_t ah[4][4], al[4][4];
#pragma unroll
            for (int mi = 0; mi < 4; mi++) {
                const int ra = wm * 64 + mi * 16 + la15;
                const uint32_t rbase = sA + ra * 128;
                const int ch = 2 * ks + aHi;
                LDSM4(ah[mi][0], ah[mi][1], ah[mi][2], ah[mi][3],
                      rbase + ((ch ^ (ra & 7)) << 4));
                LDSM4(al[mi][0], al[mi][1], al[mi][2], al[mi][3],
                      rbase + (((ch ^ 4) ^ (ra & 7)) << 4));
            }
#pragma unroll
            for (int p = 0; p < 2; p++) {
                const int rb = nwB + p * 16 + rbl;
                const uint32_t rbase = sB + rb * 128;
                const int ch = 2 * ks + bHi;
                uint32_t bh0, bh1, bh2, bh3, bl0, bl1, bl2, bl3;
                LDSM4(bh0, bh1, bh2, bh3, rbase + ((ch ^ (rb & 7)) << 4));
                LDSM4(bl0, bl1, bl2, bl3, rbase + (((ch ^ 4) ^ (rb & 7)) << 4));
#pragma unroll
                for (int mi = 0; mi < 4; mi++) {
                    MMA_BF16(acc[mi][2*p],   ah[mi][0], ah[mi][1], ah[mi][2], ah[mi][3], bh0, bh1);
                    MMA_BF16(acc[mi][2*p+1], ah[mi][0], ah[mi][1], ah[mi][2], ah[mi][3], bh2, bh3);
                }
#pragma unroll
                for (int mi = 0; mi < 4; mi++) {
                    MMA_BF16(acc[mi][2*p],   al[mi][0], al[mi][1], al[mi][2], al[mi][3], bh0, bh1);
                    MMA_BF16(acc[mi][2*p+1], al[mi][0], al[mi][1], al[mi][2], al[mi][3], bh2, bh3);
                }
#pragma unroll
                for (int mi = 0; mi < 4; mi++) {
                    MMA_BF16(acc[mi][2*p],   ah[mi][0], ah[mi][1], ah[mi][2], ah[mi][3], bl0, bl1);
                    MMA_BF16(acc[mi][2*p+1], ah[mi][0], ah[mi][1], ah[mi][2], ah[mi][3], bl2, bl3);
                }
            }
        }
    };

    const int ktiles = Kw / 16;
    issue(0, 0);
    if (ktiles > 1) issue(16, 1);
    for (int t = 0; t < ktiles; t++) {
        if (t + 1 < ktiles) CP_WAIT1(); else CP_WAIT0();
        __syncthreads();
        compute(t % 3);
        if (t + 2 < ktiles) issue((t + 2) * 16, (t + 2) % 3);
    }

#pragma unroll
    for (int mi = 0; mi < 4; mi++) {
        const int r0 = row0 + wm * 64 + mi * 16 + g;
#pragma unroll
        for (int ni = 0; ni < 4; ni++) {
            const int c = col0 + nwB + ni * 8 + tig * 2;
            float f0 = acc[mi][ni][0], f1 = acc[mi][ni][1];
            float f2 = acc[mi][ni][2], f3 = acc[mi][ni][3];
            if (BIAS) {
                const float2 bb = *(const float2*)&bias[c];
                f0 += bb.x; f1 += bb.y; f2 += bb.x; f3 += bb.y;
            }
            if (OUTPACK) {
                const int Nw = N >> 1, wc = c >> 1;
                uint32_t h0 = bfpack(f0, f1), h1 = bfpack(f2, f3);
                Ch[(size_t)r0 * Nw + wc]       = h0;
                Cl[(size_t)r0 * Nw + wc]       = bfres(f0, f1, h0);
                Ch[(size_t)(r0 + 8) * Nw + wc] = h1;
                Cl[(size_t)(r0 + 8) * Nw + wc] = bfres(f2, f3, h1);
            } else {
                *(float2*)&C[(size_t)r0 * N + c]       = make_float2(f0, f1);
                *(float2*)&C[(size_t)(r0 + 8) * N + c] = make_float2(f2, f3);
            }
        }
    }
}

// ============================================================================
// gemm_h: plain fp16 GEMM, LDSM loads, 3-stage cp.async pipeline.
// A:[M][Kw] row pack; B:[N][Kw] k-major pack (C = A·B^T over k).
// Block tile 128x128x(64 k = 32 words); word w of row r at
// r*32 + ((w>>2)^(r&7))*4 + (w&3). One __syncthreads per k-tile.
// ============================================================================
template<int OUTPACK, int BIAS, int RELU>
__global__ void __launch_bounds__(256, 2)
gemm_h(const uint32_t* __restrict__ A, const uint32_t* __restrict__ B,
       const float* __restrict__ bias,
       float* __restrict__ C, uint32_t* __restrict__ Cp,
       int M, int N, int Kw,
       size_t sAw, size_t sBw, size_t sCo)
{
    A += (size_t)blockIdx.z * sAw;
    B += (size_t)blockIdx.z * sBw;
    if (OUTPACK) Cp += (size_t)blockIdx.z * sCo;
    else         C  += (size_t)blockIdx.z * sCo;

    extern __shared__ uint32_t smh[];   // 3 bufs x (A 4096 + B 4096) words = 96KB
    const uint32_t smbase = (uint32_t)__cvta_generic_to_shared(smh);

    const int tid  = threadIdx.x;
    const int lane = tid & 31;
    const int wid  = tid >> 5;
    const int g    = lane >> 2;
    const int tig  = lane & 3;
    const int wm   = wid & 1;
    const int wn   = wid >> 1;
    const int row0 = blockIdx.y * 128;
    const int col0 = blockIdx.x * 128;
    const int nwB  = wn * 32;

    const int aHi  = lane >> 4;
    const int la15 = lane & 15;
    const int bHi  = (lane >> 3) & 1;
    const int rbl  = (lane & 7) + ((lane >> 4) << 3);

    float acc[4][4][4];
#pragma unroll
    for (int mi = 0; mi < 4; mi++)
#pragma unroll
        for (int ni = 0; ni < 4; ni++)
#pragma unroll
            for (int j = 0; j < 4; j++) acc[mi][ni][j] = 0.f;

    auto issue = [&](int ktw, int s) {
        const uint32_t sa = smbase + s * (8192 * 4);
        const uint32_t sb = sa + 4096 * 4;
#pragma unroll
        for (int i = 0; i < 4; i++) {                 // A: 128 rows x 8 chunks
            int flat = i * 256 + tid;
            int r = flat >> 3, c = flat & 7;
            const uint32_t* src = A + (size_t)(row0 + r) * Kw + ktw + c * 4;
            uint32_t dst = sa + (r * 32 + ((c ^ (r & 7)) << 2)) * 4;
            CP16(dst, src);
        }
#pragma unroll
        for (int i = 0; i < 4; i++) {                 // B: 128 rows x 8 chunks
            int flat = i * 256 + tid;
            int r = flat >> 3, c = flat & 7;
            const uint32_t* src = B + (size_t)(col0 + r) * Kw + ktw + c * 4;
            uint32_t dst = sb + (r * 32 + ((c ^ (r & 7)) << 2)) * 4;
            CP16(dst, src);
        }
        CP_COMMIT();
    };

    auto compute = [&](int s) {
        const uint32_t sA = smbase + s * (8192 * 4);
        const uint32_t sB = sA + 4096 * 4;
#pragma unroll
        for (int ks = 0; ks < 4; ks++) {
            uint32_t a[4][4];
#pragma unroll
            for (int mi = 0; mi < 4; mi++) {
                const int ra = wm * 64 + mi * 16 + la15;
                LDSM4(a[mi][0], a[mi][1], a[mi][2], a[mi][3],
                      sA + ra * 128 + (((2 * ks + aHi) ^ (ra & 7)) << 4));
            }
#pragma unroll
            for (int p = 0; p < 2; p++) {
                const int rb = nwB + p * 16 + rbl;
                uint32_t b0, b1, b2, b3;
                LDSM4(b0, b1, b2, b3,
                      sB + rb * 128 + (((2 * ks + bHi) ^ (rb & 7)) << 4));
#pragma unroll
                for (int mi = 0; mi < 4; mi++) {
                    MMA_F16(acc[mi][2*p],   a[mi][0], a[mi][1], a[mi][2], a[mi][3], b0, b1);
                    MMA_F16(acc[mi][2*p+1], a[mi][0], a[mi][1], a[mi][2], a[mi][3], b2, b3);
                }
            }
        }
    };

    const int ktiles = Kw / 32;
    issue(0, 0);
    if (ktiles > 1) issue(32, 1);
    for (int t = 0; t < ktiles; t++) {
        if (t + 1 < ktiles) CP_WAIT1(); else CP_WAIT0();
        __syncthreads();
        compute(t % 3);
        if (t + 2 < ktiles) issue((t + 2) * 32, (t + 2) % 3);
    }

#pragma unroll
    for (int mi = 0; mi < 4; mi++) {
        const int r0 = row0 + wm * 64 + mi * 16 + g;
#pragma unroll
        for (int ni = 0; ni < 4; ni++) {
            const int c = col0 + nwB + ni * 8 + tig * 2;
            float f0 = acc[mi][ni][0], f1 = acc[mi][ni][1];
            float f2 = acc[mi][ni][2], f3 = acc[mi][ni][3];
            if (BIAS) {
                const float2 bb = *(const float2*)&bias[c];
                f0 += bb.x; f1 += bb.y; f2 += bb.x; f3 += bb.y;
            }
            if (RELU) {
                f0 = fmaxf(f0, 0.f); f1 = fmaxf(f1, 0.f);
                f2 = fmaxf(f2, 0.f); f3 = fmaxf(f3, 0.f);
            }
            if (OUTPACK) {
                const int Nw = N >> 1, wc = c >> 1;
                Cp[(size_t)r0 * Nw + wc]       = hpack(f0, f1);
                Cp[(size_t)(r0 + 8) * Nw + wc] = hpack(f2, f3);
            } else {
                *(float2*)&C[(size_t)r0 * N + c]       = make_float2(f0, f1);
                *(float2*)&C[(size_t)(r0 + 8) * N + c] = make_float2(f2, f3);
            }
        }
    }
}

// ---------------- pre-pass kernels ------------------------------------------
__global__ void pack_src2(const float* __restrict__ src,
                          uint32_t* __restrict__ Sh, uint32_t* __restrict__ Sl,
                          uint32_t* __restrict__ SrcH)
{
    const size_t row = blockIdx.x;
    const int t = threadIdx.x;
#pragma unroll
    for (int j = 0; j < 2; j++) {
        const int p = t + j * 256;
        const float2 v = *(const float2*)(src + row * EMBED + 2 * p);
        uint32_t h = bfpack(v.x, v.y);
        Sh[row * (EMBED/2) + p] = h;
        Sl[row * (EMBED/2) + p] = bfres(v.x, v.y, h);
        SrcH[row * (EMBED/2) + p] = hpack(v.x, v.y);
    }
}

// tiled transpose-pack: A[K x N] f32 -> At[N][K/2] fp16x2 (scalar tile stores)
__global__ void tpack_h(const float* __restrict__ A, uint32_t* __restrict__ At,
                        int K, int N, size_t sA, size_t sAt)
{
    A  += (size_t)blockIdx.z * sA;
    At += (size_t)blockIdx.z * sAt;
    __shared__ float tile[64][65];
    const int k0 = blockIdx.y * 64, n0 = blockIdx.x * 64;
    const int t = threadIdx.x;
#pragma unroll
    for (int i = 0; i < 4; i++) {
        int flat = i * 256 + t;
        int r = flat >> 4, c = (flat & 15) * 4;
        float4 v = *(const float4*)(A + (size_t)(k0 + r) * N + n0 + c);
        tile[r][c]     = v.x;
        tile[r][c + 1] = v.y;
        tile[r][c + 2] = v.z;
        tile[r][c + 3] = v.w;
    }
    __syncthreads();
#pragma unroll
    for (int i = 0; i < 8; i++) {
        int flat = i * 256 + t;
        int n = flat >> 5, w = flat & 31;
        At[(size_t)(n0 + n) * (K >> 1) + (k0 >> 1) + w] =
            hpack(tile[2 * w][n], tile[2 * w + 1][n]);
    }
}

// tiled transpose-pack: W[K x N] f32 -> Wh/Wl[N][K/2] bf16 hi/lo
__global__ void tpack_bf(const float* __restrict__ W,
                         uint32_t* __restrict__ Wh, uint32_t* __restrict__ Wl,
                         int K, int N)
{
    __shared__ float tile[64][65];
    const int k0 = blockIdx.y * 64, n0 = blockIdx.x * 64;
    const int t = threadIdx.x;
#pragma unroll
    for (int i = 0; i < 4; i++) {
        int flat = i * 256 + t;
        int r = flat >> 4, c = (flat & 15) * 4;
        float4 v = *(const float4*)(W + (size_t)(k0 + r) * N + n0 + c);
        tile[r][c]     = v.x;
        tile[r][c + 1] = v.y;
        tile[r][c + 2] = v.z;
        tile[r][c + 3] = v.w;
    }
    __syncthreads();
#pragma unroll
    for (int i = 0; i < 8; i++) {
        int flat = i * 256 + t;
        int n = flat >> 5, w = flat & 31;
        float e0 = tile[2 * w][n], e1 = tile[2 * w + 1][n];
        uint32_t h = bfpack(e0, e1);
        Wh[(size_t)(n0 + n) * (K >> 1) + (k0 >> 1) + w] = h;
        Wl[(size_t)(n0 + n) * (K >> 1) + (k0 >> 1) + w] = bfres(e0, e1, h);
    }
}

// ---------------- softmax: read raw scores, emit packed fp16 attn ------------
__global__ void softmax_kernel(const float* __restrict__ S, uint32_t* __restrict__ AtH)
{
    const float* p = S + (size_t)blockIdx.x * SEQ;
    uint32_t* q = AtH + (size_t)blockIdx.x * (SEQ/2);
    const int tid  = threadIdx.x;     // 256 threads
    const int lane = tid & 31;
    const int warp = tid >> 5;

    float4 v0 = ((const float4*)p)[tid];
    float4 v1 = ((const float4*)p)[tid + 256];

    __shared__ float sh[8];

    float m = fmaxf(fmaxf(fmaxf(v0.x, v0.y), fmaxf(v0.z, v0.w)),
                    fmaxf(fmaxf(v1.x, v1.y), fmaxf(v1.z, v1.w)));
#pragma unroll
    for (int o = 16; o > 0; o >>= 1) m = fmaxf(m, __shfl_xor_sync(0xffffffffu, m, o));
    if (lane == 0) sh[warp] = m;
    __syncthreads();
    if (tid < 32) {
        float t = (tid < 8) ? sh[tid] : -3.402823e38f;
#pragma unroll
        for (int o = 4; o > 0; o >>= 1) t = fmaxf(t, __shfl_xor_sync(0xffffffffu, t, o));
        if (tid == 0) sh[0] = t;
    }
    __syncthreads();
    m = sh[0];
    __syncthreads();

    v0.x = __expf(v0.x - m); v0.y = __expf(v0.y - m);
    v0.z = __expf(v0.z - m); v0.w = __expf(v0.w - m);
    v1.x = __expf(v1.x - m); v1.y = __expf(v1.y - m);
    v1.z = __expf(v1.z - m); v1.w = __expf(v1.w - m);

    float s = v0.x + v0.y + v0.z + v0.w + v1.x + v1.y + v1.z + v1.w;
#pragma unroll
    for (int o = 16; o > 0; o >>= 1) s += __shfl_xor_sync(0xffffffffu, s, o);
    if (lane == 0) sh[warp] = s;
    __syncthreads();
    if (tid < 32) {
        float t = (tid < 8) ? sh[tid] : 0.f;
#pragma unroll
        for (int o = 4; o > 0; o >>= 1) t += __shfl_xor_sync(0xffffffffu, t, o);
        if (tid == 0) sh[0] = t;
    }
    __syncthreads();
    const float r = 1.f / sh[0];

    q[2*tid]           = hpack(v0.x * r, v0.y * r);
    q[2*tid + 1]       = hpack(v0.z * r, v0.w * r);
    q[512 + 2*tid]     = hpack(v1.x * r, v1.y * r);
    q[512 + 2*tid + 1] = hpack(v1.z * r, v1.w * r);
}

// ---------------- residual + layernorm: O = LN(X+Y)*g + b [, OH = fp16(O)] --
template<int WR>
__global__ void add_ln_kernel(const float* __restrict__ X, const float* __restrict__ Y,
                              const float* __restrict__ g, const float* __restrict__ b,
                              float* __restrict__ O, uint32_t* __restrict__ OH)
{
    const size_t row = blockIdx.x;
    const int tid  = threadIdx.x;   // 256 threads
    const int lane = tid & 31;
    const int warp = tid >> 5;

    const float4 x = ((const float4*)(X + row * EMBED))[tid];
    const float4 y = ((const float4*)(Y + row * EMBED))[tid];
    float4 v;
    v.x = x.x + y.x; v.y = x.y + y.y; v.z = x.z + y.z; v.w = x.w + y.w;

    float s1 = v.x + v.y + v.z + v.w;
    float s2 = v.x * v.x + v.y * v.y + v.z * v.z + v.w * v.w;

    __shared__ float sh1[8], sh2[8];
#pragma unroll
    for (int o = 16; o > 0; o >>= 1) {
        s1 += __shfl_xor_sync(0xffffffffu, s1, o);
        s2 += __shfl_xor_sync(0xffffffffu, s2, o);
    }
    if (lane == 0) { sh1[warp] = s1; sh2[warp] = s2; }
    __syncthreads();
    if (tid < 32) {
        float t1 = (tid < 8) ? sh1[tid] : 0.f;
        float t2 = (tid < 8) ? sh2[tid] : 0.f;
#pragma unroll
        for (int o = 4; o > 0; o >>= 1) {
            t1 += __shfl_xor_sync(0xffffffffu, t1, o);
            t2 += __shfl_xor_sync(0xffffffffu, t2, o);
        }
        if (tid == 0) { sh1[0] = t1; sh2[0] = t2; }
    }
    __syncthreads();

    const float inv = 1.f / (float)EMBED;
    const float mu  = sh1[0] * inv;
    const float var = sh2[0] * inv - mu * mu;
    const float r   = rsqrtf(var + 1e-5f);

    const float4 gg = ((const float4*)g)[tid];
    const float4 bb = ((const float4*)b)[tid];
    float4 o;
    o.x = (v.x - mu) * r * gg.x + bb.x;
    o.y = (v.y - mu) * r * gg.y + bb.y;
    o.z = (v.z - mu) * r * gg.z + bb.z;
    o.w = (v.w - mu) * r * gg.w + bb.w;
    ((float4*)(O + row * EMBED))[tid] = o;
    if (WR) {
        OH[row * (EMBED/2) + 2*tid]     = hpack(o.x, o.y);
        OH[row * (EMBED/2) + 2*tid + 1] = hpack(o.z, o.w);
    }
}

// ---------------- launch -----------------------------------------------------
extern "C" void kernel_launch(void* const* d_in, const int* in_sizes, int n_in,
                              void* d_out, int out_size)
{
    const float* src = (const float*)d_in[0];
    const float* Wq  = (const float*)d_in[1];
    const float* bq  = (const float*)d_in[2];
    const float* Wk  = (const float*)d_in[3];
    const float* bk  = (const float*)d_in[4];
    const float* Wv  = (const float*)d_in[5];
    const float* bv  = (const float*)d_in[6];
    const float* Wo  = (const float*)d_in[7];
    const float* bo  = (const float*)d_in[8];
    const float* W1  = (const float*)d_in[9];
    const float* b1  = (const float*)d_in[10];
    const float* W2  = (const float*)d_in[11];
    const float* b2  = (const float*)d_in[12];
    const float* g1  = (const float*)d_in[13];
    const float* be1 = (const float*)d_in[14];
    const float* g2  = (const float*)d_in[15];
    const float* be2 = (const float*)d_in[16];

    float *S, *T, *AO, *X, *Vp;
    uint32_t *SrcH, *XH, *AoH, *FH, *AtH, *VtH, *WvtH, *WotH, *W1tH, *W2tH;
    uint32_t *Sh, *Sl, *Qh, *Ql, *Kh, *Kl, *Wqh, *Wql, *Wkh, *Wkl;
    cudaGetSymbolAddress((void**)&S,    g_S);
    cudaGetSymbolAddress((void**)&T,    g_T);
    cudaGetSymbolAddress((void**)&AO,   g_AO);
    cudaGetSymbolAddress((void**)&X,    g_X);
    cudaGetSymbolAddress((void**)&Vp,   g_Vp);
    cudaGetSymbolAddress((void**)&SrcH, g_SrcH);
    cudaGetSymbolAddress((void**)&XH,   g_XH);
    cudaGetSymbolAddress((void**)&AoH,  g_AoH);
    cudaGetSymbolAddress((void**)&FH,   g_FH);
    cudaGetSymbolAddress((void**)&AtH,  g_AtH);
    cudaGetSymbolAddress((void**)&VtH,  g_VtH);
    cudaGetSymbolAddress((void**)&WvtH, g_WvtH);
    cudaGetSymbolAddress((void**)&WotH, g_WotH);
    cudaGetSymbolAddress((void**)&W1tH, g_W1tH);
    cudaGetSymbolAddress((void**)&W2tH, g_W2tH);
    cudaGetSymbolAddress((void**)&Sh,   g_Sh);
    cudaGetSymbolAddress((void**)&Sl,   g_Sl);
    cudaGetSymbolAddress((void**)&Qh,   g_Qh);
    cudaGetSymbolAddress((void**)&Ql,   g_Ql);
    cudaGetSymbolAddress((void**)&Kh,   g_Kh);
    cudaGetSymbolAddress((void**)&Kl,   g_Kl);
    cudaGetSymbolAddress((void**)&Wqh,  g_Wqh);
    cudaGetSymbolAddress((void**)&Wql,  g_Wql);
    cudaGetSymbolAddress((void**)&Wkh,  g_Wkh);
    cudaGetSymbolAddress((void**)&Wkl,  g_Wkl);

    const int SMEM = 98304;   // 3 stages x 32KB
    cudaFuncSetAttribute(gemm_p<1,1>,   cudaFuncAttributeMaxDynamicSharedMemorySize, SMEM);
    cudaFuncSetAttribute(gemm_p<0,0>,   cudaFuncAttributeMaxDynamicSharedMemorySize, SMEM);
    cudaFuncSetAttribute(gemm_h<0,1,0>, cudaFuncAttributeMaxDynamicSharedMemorySize, SMEM);
    cudaFuncSetAttribute(gemm_h<1,0,0>, cudaFuncAttributeMaxDynamicSharedMemorySize, SMEM);
    cudaFuncSetAttribute(gemm_h<1,1,1>, cudaFuncAttributeMaxDynamicSharedMemorySize, SMEM);

    const int KW = EMBED / 2;                       // 512 words
    const size_t sQEw = (size_t)SEQ * KW;           // per-batch packed act stride
    const size_t sSS  = (size_t)SEQ * SEQ;          // per-batch score stride (f32)
    const size_t sSSw = sSS / 2;                    // per-batch attn words
    const size_t sVt  = (size_t)EMBED * (SEQ/2);    // per-batch V^T words

    // launch order arranged so launch #4 (ncu capture slot) = gemm_h V-proj
    pack_src2<<<NROWS, 256>>>(src, Sh, Sl, SrcH);                       // 1
    tpack_h <<<dim3(16,16), 256>>>(Wv, WvtH, EMBED, EMBED, 0, 0);       // 2
    tpack_bf<<<dim3(16,16), 256>>>(Wq, Wqh, Wql, EMBED, EMBED);         // 3
    gemm_h<0,1,0><<<dim3(EMBED/128, NROWS/128), 256, SMEM>>>(SrcH, WvtH, bv,
        Vp, nullptr, NROWS, EMBED, KW, 0, 0, 0);                        // 4 <- profiled
    tpack_bf<<<dim3(16,16), 256>>>(Wk, Wkh, Wkl, EMBED, EMBED);         // 5
    tpack_h <<<dim3(16,16), 256>>>(Wo, WotH, EMBED, EMBED, 0, 0);
    tpack_h <<<dim3(64,16), 256>>>(W1, W1tH, EMBED, DFF,   0, 0);
    tpack_h <<<dim3(16,64), 256>>>(W2, W2tH, DFF,   EMBED, 0, 0);

    // Q, K projections (bf16 3-term, packed out)
    gemm_p<1,1><<<dim3(EMBED/128, NROWS/128), 256, SMEM>>>(Sh, Sl, Wqh, Wql, bq,
        nullptr, Qh, Ql, NROWS, EMBED, KW, 0, 0, 0);
    gemm_p<1,1><<<dim3(EMBED/128, NROWS/128), 256, SMEM>>>(Sh, Sl, Wkh, Wkl, bk,
        nullptr, Kh, Kl, NROWS, EMBED, KW, 0, 0, 0);

    // V^T pack per batch
    tpack_h<<<dim3(16, 32, NBATCH), 256>>>(Vp, VtH, SEQ, EMBED,
        (size_t)SEQ * EMBED, sVt);

    // scores = Q @ K^T (bf16 3-term) -> f32
    gemm_p<0,0><<<dim3(SEQ/128, SEQ/128, NBATCH), 256, SMEM>>>(Qh, Ql, Kh, Kl, nullptr,
        S, nullptr, nullptr, SEQ, SEQ, KW, sQEw, sQEw, sSS);

    // softmax -> packed fp16 attn
    softmax_kernel<<<NROWS, 256>>>(S, AtH);

    // ao = attn @ V (fp16) -> packed
    gemm_h<1,0,0><<<dim3(EMBED/128, SEQ/128, NBATCH), 256, SMEM>>>(AtH, VtH, nullptr,
        nullptr, AoH, SEQ, EMBED, SEQ/2, sSSw, sVt, sQEw);

    // out-proj (fp16) -> f32
    gemm_h<0,1,0><<<dim3(EMBED/128, NROWS/128), 256, SMEM>>>(AoH, WotH, bo,
        AO, nullptr, NROWS, EMBED, KW, 0, 0, 0);

    add_ln_kernel<1><<<NROWS, 256>>>(src, AO, g1, be1, X, XH);

    // ff1 = relu(x @ W1 + b1) (fp16) -> packed
    gemm_h<1,1,1><<<dim3(DFF/128, NROWS/128), 256, SMEM>>>(XH, W1tH, b1,
        nullptr, FH, NROWS, DFF, KW, 0, 0, 0);

    // ff2 (fp16) -> f32
    gemm_h<0,1,0><<<dim3(EMBED/128, NROWS/128), 256, SMEM>>>(FH, W2tH, b2,
        T, nullptr, NROWS, EMBED, DFF/2, 0, 0, 0);

    add_ln_kernel<0><<<NROWS, 256>>>(X, T, g2, be2, (float*)d_out, nullptr);
}